// round 14
// baseline (speedup 1.0000x reference)
#include <cuda_runtime.h>
#include <cuda_bf16.h>
#include <cuda_fp16.h>
#include <cstdint>

#define BB 8
#define CC 512
#define NN 4096
#define DD 64

// ---------------- scratch ----------------------------------------------------
__device__ __nv_bfloat16 g_attn[(long)BB * NN * NN];     // 256 MB attn[n][m] = exp(qk)
__device__ __nv_bfloat16 g_xbf[(long)BB * CC * NN];      // x hi
__device__ __nv_bfloat16 g_xlo[(long)BB * CC * NN];      // x lo
__device__ __nv_bfloat16 g_v[(long)BB * CC * NN];
__device__ __nv_bfloat16 g_Wvbf[CC * CC];
__device__ __nv_bfloat16 g_Wqk2[128 * 1536];             // [d][hW|lW|hW]
__device__ __half g_qt16[(long)BB * NN * DD];            // [b][n][d]
__device__ __half g_k16[(long)BB * DD * NN];             // [b][d][m]
__device__ float g_colpart[(long)BB * 32 * NN];
__device__ float g_colsum[BB * NN];

// ---------------- helpers ----------------------------------------------------
__device__ __forceinline__ float fast_exp(float x) {
    float t = x * 1.4426950408889634f;
    float z = t + 12582912.0f;
    int   n = __float_as_int(z) - 0x4B400000;
    float fi = z - 12582912.0f;
    float f = t - fi;
    float p = 1.3333558e-3f;
    p = fmaf(p, f, 9.6181291e-3f);
    p = fmaf(p, f, 5.5504109e-2f);
    p = fmaf(p, f, 2.4022651e-1f);
    p = fmaf(p, f, 6.9314718e-1f);
    p = fmaf(p, f, 1.0f);
    return p * __int_as_float((n + 127) << 23);
}
__device__ __forceinline__ void ldsm_x4(unsigned r[4], uint32_t a) {
    asm volatile("ldmatrix.sync.aligned.m8n8.x4.shared.b16 {%0,%1,%2,%3}, [%4];"
                 : "=r"(r[0]), "=r"(r[1]), "=r"(r[2]), "=r"(r[3]) : "r"(a));
}
__device__ __forceinline__ void ldsm_x4t(unsigned r[4], uint32_t a) {
    asm volatile("ldmatrix.sync.aligned.m8n8.x4.trans.shared.b16 {%0,%1,%2,%3}, [%4];"
                 : "=r"(r[0]), "=r"(r[1]), "=r"(r[2]), "=r"(r[3]) : "r"(a));
}
__device__ __forceinline__ void mma_bf16(float c[4], const unsigned a[4], const unsigned b2[2]) {
    asm volatile("mma.sync.aligned.m16n8k16.row.col.f32.bf16.bf16.f32 "
                 "{%0,%1,%2,%3},{%4,%5,%6,%7},{%8,%9},{%0,%1,%2,%3};"
                 : "+f"(c[0]), "+f"(c[1]), "+f"(c[2]), "+f"(c[3])
                 : "r"(a[0]), "r"(a[1]), "r"(a[2]), "r"(a[3]), "r"(b2[0]), "r"(b2[1]));
}
__device__ __forceinline__ void mma_f16(float c[4], const unsigned a[4], const unsigned b2[2]) {
    asm volatile("mma.sync.aligned.m16n8k16.row.col.f32.f16.f16.f32 "
                 "{%0,%1,%2,%3},{%4,%5,%6,%7},{%8,%9},{%0,%1,%2,%3};"
                 : "+f"(c[0]), "+f"(c[1]), "+f"(c[2]), "+f"(c[3])
                 : "r"(a[0]), "r"(a[1]), "r"(a[2]), "r"(a[3]), "r"(b2[0]), "r"(b2[1]));
}
__device__ __forceinline__ void cp16(uint32_t s, const void* g) {
    asm volatile("cp.async.cg.shared.global [%0], [%1], 16;" :: "r"(s), "l"(g));
}
__device__ __forceinline__ uint32_t smem_u32(const void* p) {
    return (uint32_t)__cvta_generic_to_shared(p);
}

// ---------------- merged converts --------------------------------------------
__global__ void cvt_all_kernel(const float* __restrict__ x, const float* __restrict__ Wv,
                               const float* __restrict__ Wq, const float* __restrict__ Wk) {
    int bid = blockIdx.x;
    int tid = threadIdx.x;
    if (bid < 16384) {
        long i = ((long)bid * 256 + tid) * 4;
        float4 v = *(const float4*)(x + i);
        float h0 = __bfloat162float(__float2bfloat16(v.x));
        float h1 = __bfloat162float(__float2bfloat16(v.y));
        float h2 = __bfloat162float(__float2bfloat16(v.z));
        float h3 = __bfloat162float(__float2bfloat16(v.w));
        *(__nv_bfloat162*)(g_xbf + i)     = __floats2bfloat162_rn(h0, h1);
        *(__nv_bfloat162*)(g_xbf + i + 2) = __floats2bfloat162_rn(h2, h3);
        *(__nv_bfloat162*)(g_xlo + i)     = __floats2bfloat162_rn(v.x - h0, v.y - h1);
        *(__nv_bfloat162*)(g_xlo + i + 2) = __floats2bfloat162_rn(v.z - h2, v.w - h3);
    } else if (bid < 16640) {
        long i = ((long)(bid - 16384) * 256 + tid) * 4;
        float4 v = *(const float4*)(Wv + i);
        *(__nv_bfloat162*)(g_Wvbf + i)     = __floats2bfloat162_rn(v.x, v.y);
        *(__nv_bfloat162*)(g_Wvbf + i + 2) = __floats2bfloat162_rn(v.z, v.w);
    } else {
        int i = (bid - 16640) * 256 + tid;
        int d = i >> 9, c = i & 511;
        float v = (d < 64) ? Wq[d * 512 + c] : Wk[(d - 64) * 512 + c];
        __nv_bfloat16 h = __float2bfloat16(v);
        __nv_bfloat16 l = __float2bfloat16(v - __bfloat162float(h));
        g_Wqk2[d * 1536 + c] = h;
        g_Wqk2[d * 1536 + 512 + c] = l;
        g_Wqk2[d * 1536 + 1024 + c] = h;
    }
}

// ---------------- qk projection (bf16 split GEMM K=1536), 4-stage paired -----
// dynamic smem: 4 stages A(10240)+B(8704); tq transpose buffer aliases stages.
__global__ __launch_bounds__(256, 2)
void qkproj_mma_kernel() {
    constexpr int NIT = 48;
    extern __shared__ __align__(16) char pdsm[];
    __nv_bfloat16* As = (__nv_bfloat16*)pdsm;       // 4 * 5120 bf16
    __nv_bfloat16* Bs = As + 4 * 5120;              // 4 * 4352 bf16
    __half* tq = (__half*)pdsm;                     // 128*68*2 = 17408B, post-loop
    int b = blockIdx.z;
    int nbase = blockIdx.x * 128;
    int tid = threadIdx.x, lane = tid & 31, warp = tid >> 5;
    int wm = warp & 3, wn = warp >> 2;
    const __nv_bfloat16* xh = g_xbf + (long)b * CC * NN;
    const __nv_bfloat16* xl = g_xlo + (long)b * CC * NN;

    float acc[2][8][4];
#pragma unroll
    for (int t = 0; t < 2; t++)
#pragma unroll
        for (int j = 0; j < 8; j++)
#pragma unroll
            for (int e = 0; e < 4; e++) acc[t][j][e] = 0.f;

    uint32_t as0 = smem_u32(As), bs0 = smem_u32(Bs);
    uint32_t a_st = ((tid >> 2) * 40 + (tid & 3) * 8) * 2;
    uint32_t b_st = ((tid >> 4) * 136 + (tid & 15) * 8) * 2;
    const long a_g0 = (long)(tid >> 2) * 1536 + (tid & 3) * 8;
    const long b_g0 = (long)(tid >> 4) * NN + nbase + (tid & 15) * 8;
    uint32_t a_off = ((wm * 32 + (lane & 15)) * 40 + (lane >> 4) * 8) * 2;
    uint32_t b_off = ((lane & 15) * 136 + wn * 64 + (lane >> 4) * 8) * 2;

    auto issue = [&](int c, int st) {
        uint32_t ab = as0 + st * 10240, bb = bs0 + st * 8704;
        cp16(ab + a_st, g_Wqk2 + a_g0 + c * 32);
        cp16(ab + a_st + 64 * 80, g_Wqk2 + a_g0 + 64L * 1536 + c * 32);
        const __nv_bfloat16* Bsrc =
            (c < 16) ? (xh + (long)(c * 32) * NN)
                     : (c < 32) ? (xh + (long)((c - 16) * 32) * NN)
                                : (xl + (long)((c - 32) * 32) * NN);
        cp16(bb + b_st, Bsrc + b_g0);
        cp16(bb + b_st + 16 * 272, Bsrc + b_g0 + 16L * NN);
        asm volatile("cp.async.commit_group;" ::);
    };
    auto compute_stage = [&](int st) {
        uint32_t aa = as0 + st * 10240 + a_off;
        uint32_t bb2 = bs0 + st * 8704 + b_off;
#pragma unroll
        for (int ks = 0; ks < 2; ks++) {
            unsigned af[2][4];
            ldsm_x4(af[0], aa + ks * 32);
            ldsm_x4(af[1], aa + 1280 + ks * 32);
#pragma unroll
            for (int jp = 0; jp < 4; jp++) {
                unsigned bf[4];
                ldsm_x4t(bf, bb2 + jp * 32 + ks * 4352);
                mma_bf16(acc[0][2 * jp],     af[0], bf);
                mma_bf16(acc[0][2 * jp + 1], af[0], bf + 2);
                mma_bf16(acc[1][2 * jp],     af[1], bf);
                mma_bf16(acc[1][2 * jp + 1], af[1], bf + 2);
            }
        }
    };

    issue(0, 0);
    issue(1, 1);
    for (int it = 0; it < NIT; it += 2) {
        if (it + 2 < NIT) {
            issue(it + 2, (it + 2) & 3);
            issue(it + 3, (it + 3) & 3);
            asm volatile("cp.async.wait_group 2;" ::);
        } else {
            asm volatile("cp.async.wait_group 0;" ::);
        }
        __syncthreads();
        compute_stage(it & 3);
        compute_stage((it + 1) & 3);
        __syncthreads();
    }

    int row0 = wm * 32 + (lane >> 2);
    int col0l = wn * 64 + (lane & 3) * 2;   // local n
#pragma unroll
    for (int t = 0; t < 2; t++)
#pragma unroll
        for (int rr = 0; rr < 2; rr++) {
            int d = row0 + t * 16 + rr * 8;
            if (d < 64) {
#pragma unroll
                for (int j = 0; j < 8; j++) {
                    int c = col0l + j * 8;
                    tq[c * 68 + d]       = __float2half(acc[t][j][rr * 2]);
                    tq[(c + 1) * 68 + d] = __float2half(acc[t][j][rr * 2 + 1]);
                }
            } else {
                __half* dst = g_k16 + ((long)b * DD + d - 64) * NN + nbase;
#pragma unroll
                for (int j = 0; j < 8; j++) {
                    *(__half2*)(dst + col0l + j * 8) =
                        __floats2half2_rn(acc[t][j][rr * 2], acc[t][j][rr * 2 + 1]);
                }
            }
        }
    __syncthreads();
    {
        int n = tid >> 1, dh = (tid & 1) * 32;
        __half* dst = g_qt16 + (long)b * NN * DD + (long)(nbase + n) * DD + dh;
        const __half* src = tq + n * 68 + dh;
#pragma unroll
        for (int c4 = 0; c4 < 8; c4++)
            *(uint2*)(dst + c4 * 4) = *(const uint2*)(src + c4 * 4);
    }
}

// ---------------- qk fp16 GEMM (K=64) + exp + smem-staged attn store ---------
__global__ __launch_bounds__(256, 2)
void qk_mma_kernel() {
    constexpr int KD = 64;
    constexpr int CTS = 136;
    extern __shared__ __align__(16) char qsm[];
    __half* As = (__half*)qsm;
    __half* Bs = (__half*)(qsm + 20480);
    __nv_bfloat16* Ct = (__nv_bfloat16*)qsm;
    __shared__ float cred[4 * 128];
    int b = blockIdx.z;
    const __half* A  = g_qt16 + (long)b * NN * KD;
    const __half* Bm = g_k16  + (long)b * KD * NN;
    int mbase = blockIdx.y * 128;
    int nbase = blockIdx.x * 128;
    int tid = threadIdx.x, lane = tid & 31, warp = tid >> 5;
    int wm = warp & 3, wn = warp >> 2;

    float acc[2][8][4];
#pragma unroll
    for (int t = 0; t < 2; t++)
#pragma unroll
        for (int j = 0; j < 8; j++)
#pragma unroll
            for (int e = 0; e < 4; e++) acc[t][j][e] = 0.f;

    uint32_t as0 = smem_u32(As), bs0 = smem_u32(Bs);
    uint32_t a_st = ((tid >> 2) * 40 + (tid & 3) * 8) * 2;
    uint32_t b_st = ((tid >> 4) * 136 + (tid & 15) * 8) * 2;
    const long a_g0 = (long)(mbase + (tid >> 2)) * KD + (tid & 3) * 8;
    const long b_g0 = (long)(tid >> 4) * NN + nbase + (tid & 15) * 8;
    uint32_t a_off = ((wm * 32 + (lane & 15)) * 40 + (lane >> 4) * 8) * 2;
    uint32_t b_off = ((lane & 15) * 136 + wn * 64 + (lane >> 4) * 8) * 2;

#define QK_ISSUE(k0, st)                                                        \
    {                                                                           \
        uint32_t ab = as0 + (st) * 10240, bb = bs0 + (st) * 8704;               \
        cp16(ab + a_st, A + a_g0 + (k0));                                       \
        cp16(ab + a_st + 64 * 80, A + a_g0 + 64L * KD + (k0));                  \
        cp16(bb + b_st, Bm + b_g0 + (long)(k0) * NN);                           \
        cp16(bb + b_st + 16 * 272, Bm + b_g0 + (long)((k0) + 16) * NN);         \
        asm volatile("cp.async.commit_group;" ::);                              \
    }

    QK_ISSUE(0, 0);
    QK_ISSUE(32, 1);
#pragma unroll
    for (int it = 0; it < 2; it++) {
        if (it == 0) {
            asm volatile("cp.async.wait_group 1;" ::);
        } else {
            asm volatile("cp.async.wait_group 0;" ::);
        }
        __syncthreads();
        uint32_t aa = as0 + it * 10240 + a_off;
        uint32_t bbq = bs0 + it * 8704 + b_off;
#pragma unroll
        for (int ks = 0; ks < 2; ks++) {
            unsigned af[2][4];
            ldsm_x4(af[0], aa + ks * 32);
            ldsm_x4(af[1], aa + 1280 + ks * 32);
#pragma unroll
            for (int jp = 0; jp < 4; jp++) {
                unsigned bf[4];
                ldsm_x4t(bf, bbq + jp * 32 + ks * 4352);
                mma_f16(acc[0][2 * jp],     af[0], bf);
                mma_f16(acc[0][2 * jp + 1], af[0], bf + 2);
                mma_f16(acc[1][2 * jp],     af[1], bf);
                mma_f16(acc[1][2 * jp + 1], af[1], bf + 2);
            }
        }
    }
#undef QK_ISSUE

    __syncthreads();

    int row0l = wm * 32 + (lane >> 2);
    int col0l = wn * 64 + (lane & 3) * 2;
    float colp[8][2];
#pragma unroll
    for (int j = 0; j < 8; j++) { colp[j][0] = 0.f; colp[j][1] = 0.f; }
#pragma unroll
    for (int t = 0; t < 2; t++)
#pragma unroll
        for (int j = 0; j < 8; j++) {
            float e0 = fast_exp(acc[t][j][0]);
            float e1 = fast_exp(acc[t][j][1]);
            float e2 = fast_exp(acc[t][j][2]);
            float e3 = fast_exp(acc[t][j][3]);
            colp[j][0] += e0 + e2;
            colp[j][1] += e1 + e3;
            int r = row0l + t * 16, c = col0l + j * 8;
            *(__nv_bfloat162*)(Ct + r * CTS + c)       = __floats2bfloat162_rn(e0, e1);
            *(__nv_bfloat162*)(Ct + (r + 8) * CTS + c) = __floats2bfloat162_rn(e2, e3);
        }
#pragma unroll
    for (int off = 16; off >= 4; off >>= 1)
#pragma unroll
        for (int j = 0; j < 8; j++) {
            colp[j][0] += __shfl_xor_sync(0xffffffffu, colp[j][0], off);
            colp[j][1] += __shfl_xor_sync(0xffffffffu, colp[j][1], off);
        }
    if ((lane >> 2) == 0) {
#pragma unroll
        for (int j = 0; j < 8; j++) {
            cred[wm * 128 + wn * 64 + j * 8 + (lane & 3) * 2]     = colp[j][0];
            cred[wm * 128 + wn * 64 + j * 8 + (lane & 3) * 2 + 1] = colp[j][1];
        }
    }
    __syncthreads();

    __nv_bfloat16* ab = g_attn + ((long)b << 24);
    {
        int row = tid >> 1;
        int half = tid & 1;
        const __nv_bfloat16* src = Ct + row * CTS;
        __nv_bfloat16* dstg = ab + (long)(mbase + row) * NN + nbase;
#pragma unroll
        for (int j2 = 0; j2 < 8; j2++) {
            int cchunk = (half + 2 * j2) * 8;
            *(uint4*)(dstg + cchunk) = *(const uint4*)(src + cchunk);
        }
    }
    if (tid < 128) {
        float s = cred[tid] + cred[128 + tid] + cred[256 + tid] + cred[384 + tid];
        g_colpart[((long)b * 32 + blockIdx.y) * NN + nbase + tid] = s;
    }
}

// ---------------- column sum finalize ----------------------------------------
__global__ void rsum_kernel(const float* __restrict__ gamma) {
    int i = blockIdx.x * 256 + threadIdx.x;
    int b = i >> 12, col = i & 4095;
    const float* p = g_colpart + (long)b * 32 * NN + col;
    float s = 0.f;
#pragma unroll
    for (int t = 0; t < 32; t++) s += p[(long)t * NN];
    g_colsum[i] = gamma[0] / s;
}

// ---------------- v-proj (bf16, 128x128 tile, 4-stage paired) ----------------
__global__ __launch_bounds__(256)
void vproj_kernel() {
    constexpr int KDIM = 512;
    constexpr int NIT = KDIM / 32;
    extern __shared__ __align__(16) char dsm[];
    __nv_bfloat16* As = (__nv_bfloat16*)dsm;       // 4 * 5120 bf16
    __nv_bfloat16* Bs = As + 4 * 5120;             // 4 * 4352 bf16
    int b = blockIdx.z;
    const __nv_bfloat16* A  = g_Wvbf;
    const __nv_bfloat16* Bm = g_xbf + (long)b * CC * NN;
    int mbase = blockIdx.y * 128, nbase = blockIdx.x * 128;
    int tid = threadIdx.x, lane = tid & 31, warp = tid >> 5;
    int wm = warp & 3, wn = warp >> 2;

    float acc[2][8][4];
#pragma unroll
    for (int t = 0; t < 2; t++)
#pragma unroll
        for (int j = 0; j < 8; j++)
#pragma unroll
            for (int e = 0; e < 4; e++) acc[t][j][e] = 0.f;

    uint32_t as0 = smem_u32(As), bs0 = smem_u32(Bs);
    uint32_t a_st = ((tid >> 2) * 40 + (tid & 3) * 8) * 2;
    uint32_t b_st = ((tid >> 4) * 136 + (tid & 15) * 8) * 2;
    const long a_g0 = (long)(mbase + (tid >> 2)) * KDIM + (tid & 3) * 8;
    const long b_g0 = (long)(tid >> 4) * NN + nbase + (tid & 15) * 8;
    uint32_t a_off = ((wm * 32 + (lane & 15)) * 40 + (lane >> 4) * 8) * 2;
    uint32_t b_off = ((lane & 15) * 136 + wn * 64 + (lane >> 4) * 8) * 2;

#define VP_ISSUE(k0, st)                                                        \
    {                                                                           \
        uint32_t ab = as0 + (st) * 10240, bb = bs0 + (st) * 8704;               \
        cp16(ab + a_st, A + a_g0 + (k0));                                       \
        cp16(ab + a_st + 64 * 80, A + a_g0 + 64L * KDIM + (k0));                \
        cp16(bb + b_st, Bm + b_g0 + (long)(k0) * NN);                           \
        cp16(bb + b_st + 16 * 272, Bm + b_g0 + (long)((k0) + 16) * NN);         \
        asm volatile("cp.async.commit_group;" ::);                              \
    }

    auto compute_stage = [&](int st) {
        uint32_t aa = as0 + st * 10240 + a_off;
        uint32_t bb2 = bs0 + st * 8704 + b_off;
#pragma unroll
        for (int ks = 0; ks < 2; ks++) {
            unsigned af[2][4];
            ldsm_x4(af[0], aa + ks * 32);
            ldsm_x4(af[1], aa + 1280 + ks * 32);
#pragma unroll
            for (int jp = 0; jp < 4; jp++) {
                unsigned bf[4];
                ldsm_x4t(bf, bb2 + jp * 32 + ks * 4352);
                mma_bf16(acc[0][2 * jp],     af[0], bf);
                mma_bf16(acc[0][2 * jp + 1], af[0], bf + 2);
                mma_bf16(acc[1][2 * jp],     af[1], bf);
                mma_bf16(acc[1][2 * jp + 1], af[1], bf + 2);
            }
        }
    };

    VP_ISSUE(0, 0);
    VP_ISSUE(32, 1);
    for (int it = 0; it < NIT; it += 2) {
        if (it + 2 < NIT) {
            VP_ISSUE((it + 2) * 32, (it + 2) & 3);
            VP_ISSUE((it + 3) * 32, (it + 3) & 3);
            asm volatile("cp.async.wait_group 2;" ::);
        } else {
            asm volatile("cp.async.wait_group 0;" ::);
        }
        __syncthreads();
        compute_stage(it & 3);
        compute_stage((it + 1) & 3);
        __syncthreads();
    }
#undef VP_ISSUE

    int row0 = mbase + wm * 32 + (lane >> 2);
    int col0 = nbase + wn * 64 + (lane & 3) * 2;
    __nv_bfloat16* Vb = g_v + (long)b * CC * NN;
#pragma unroll
    for (int t = 0; t < 2; t++)
#pragma unroll
        for (int j = 0; j < 8; j++) {
            int r = row0 + t * 16, c = col0 + j * 8;
            *(__nv_bfloat162*)(Vb + (long)r * NN + c) =
                __floats2bfloat162_rn(acc[t][j][0], acc[t][j][1]);
            *(__nv_bfloat162*)(Vb + (long)(r + 8) * NN + c) =
                __floats2bfloat162_rn(acc[t][j][2], acc[t][j][3]);
        }
}

// ---------------- PV big-tile: 512 threads, 128x256 out tile, 4-stage paired -
// A = v [c][n] (128 rows), B = attn [n][m] (256 cols). Same per-warp tile as
// before (32x64); 16 warps as 4M x 4N. B smem stride 264 halfs.
__global__ __launch_bounds__(512)
void pv_big_kernel(float* __restrict__ Out, const float* __restrict__ Xres) {
    constexpr int KDIM = NN;
    constexpr int NIT = KDIM / 32;          // 128
    constexpr int ASTG = 10240;             // bytes per A stage
    constexpr int BSTG = 16896;             // bytes per B stage (32*264*2)
    extern __shared__ __align__(16) char dsm[];
    __nv_bfloat16* As = (__nv_bfloat16*)dsm;        // 4 * ASTG
    __nv_bfloat16* Bs = (__nv_bfloat16*)(dsm + 4 * ASTG);
    int b = blockIdx.z;
    const __nv_bfloat16* A  = g_v + (long)b * CC * NN;
    const __nv_bfloat16* Bm = g_attn + ((long)b << 24);
    int mbase = blockIdx.y * 128, nbase = blockIdx.x * 256;
    int tid = threadIdx.x, lane = tid & 31, warp = tid >> 5;
    int wm = warp & 3, wn = warp >> 2;      // wn in 0..3

    float acc[2][8][4];
#pragma unroll
    for (int t = 0; t < 2; t++)
#pragma unroll
        for (int j = 0; j < 8; j++)
#pragma unroll
            for (int e = 0; e < 4; e++) acc[t][j][e] = 0.f;

    uint32_t as0 = smem_u32(As), bs0 = smem_u32(Bs);
    // A fill: 512 threads x 1 cp16 = 128 rows x 4 chunks
    uint32_t a_st = ((tid >> 2) * 40 + (tid & 3) * 8) * 2;
    const long a_g0 = (long)(mbase + (tid >> 2)) * KDIM + (tid & 3) * 8;
    // B fill: 512 threads x 2 cp16 = 32 rows x 32 chunks
    uint32_t b_st = ((tid >> 4) * 264 + (tid & 15) * 8) * 2;
    const long b_g0 = (long)(tid >> 4) * NN + nbase + (tid & 15) * 8;
    uint32_t a_off = ((wm * 32 + (lane & 15)) * 40 + (lane >> 4) * 8) * 2;
    uint32_t b_off = ((lane & 15) * 264 + wn * 64 + (lane >> 4) * 8) * 2;

#define PV_ISSUE(k0, st)                                                        \
    {                                                                           \
        uint32_t ab = as0 + (st) * ASTG, bb = bs0 + (st) * BSTG;                \
        cp16(ab + a_st, A + a_g0 + (k0));                                       \
        cp16(bb + b_st, Bm + b_g0 + (long)(k0) * NN);                           \
        cp16(bb + b_st + 256, Bm + b_g0 + (long)(k0) * NN + 128);               \
        asm volatile("cp.async.commit_group;" ::);                              \
    }

    auto compute_stage = [&](int st) {
        uint32_t aa = as0 + st * ASTG + a_off;
        uint32_t bb2 = bs0 + st * BSTG + b_off;
#pragma unroll
        for (int ks = 0; ks < 2; ks++) {
            unsigned af[2][4];
            ldsm_x4(af[0], aa + ks * 32);
            ldsm_x4(af[1], aa + 1280 + ks * 32);
#pragma unroll
            for (int jp = 0; jp < 4; jp++) {
                unsigned bf[4];
                ldsm_x4t(bf, bb2 + jp * 32 + ks * 8448);
                mma_bf16(acc[0][2 * jp],     af[0], bf);
                mma_bf16(acc[0][2 * jp + 1], af[0], bf + 2);
                mma_bf16(acc[1][2 * jp],     af[1], bf);
                mma_bf16(acc[1][2 * jp + 1], af[1], bf + 2);
            }
        }
    };

    PV_ISSUE(0, 0);
    PV_ISSUE(32, 1);
    for (int it = 0; it < NIT; it += 2) {
        if (it + 2 < NIT) {
            PV_ISSUE((it + 2) * 32, (it + 2) & 3);
            PV_ISSUE((it + 3) * 32, (it + 3) & 3);
            asm volatile("cp.async.wait_group 2;" ::);
        } else {
            asm volatile("cp.async.wait_group 0;" ::);
        }
        __syncthreads();
        compute_stage(it & 3);
        compute_stage((it + 1) & 3);
        __syncthreads();
    }
#undef PV_ISSUE

    int row0 = mbase + wm * 32 + (lane >> 2);
    int col0 = nbase + wn * 64 + (lane & 3) * 2;
    float* Ob = Out + (long)b * CC * NN;
    const float* Xb = Xres + (long)b * CC * NN;
    const float* rs = g_colsum + b * NN;
#pragma unroll
    for (int j = 0; j < 8; j++) {
        int c = col0 + j * 8;
        float r0 = rs[c], r1 = rs[c + 1];
#pragma unroll
        for (int t = 0; t < 2; t++) {
            int r = row0 + t * 16;
            float2 x0 = *(const float2*)(Xb + (long)r * NN + c);
            float2 o0 = {fmaf(acc[t][j][0], r0, x0.x), fmaf(acc[t][j][1], r1, x0.y)};
            *(float2*)(Ob + (long)r * NN + c) = o0;
            float2 x1 = *(const float2*)(Xb + (long)(r + 8) * NN + c);
            float2 o1 = {fmaf(acc[t][j][2], r0, x1.x), fmaf(acc[t][j][3], r1, x1.y)};
            *(float2*)(Ob + (long)(r + 8) * NN + c) = o1;
        }
    }
}

// ---------------- launch -----------------------------------------------------
extern "C" void kernel_launch(void* const* d_in, const int* in_sizes, int n_in,
                              void* d_out, int out_size) {
    const float* x     = (const float*)d_in[0];
    const float* Wq    = (const float*)d_in[1];
    const float* Wk    = (const float*)d_in[2];
    const float* Wv    = (const float*)d_in[3];
    const float* gamma = (const float*)d_in[4];
    float* out = (float*)d_out;

    const int GEMM_SMEM = 4 * (10240 + 8704);        // 75776 (qkproj, vproj)
    const int QK_SMEM   = 20480 + 17408;             // 37888
    const int PVB_SMEM  = 4 * (10240 + 16896);       // 108544
    cudaFuncSetAttribute(qkproj_mma_kernel,
                         cudaFuncAttributeMaxDynamicSharedMemorySize, GEMM_SMEM);
    cudaFuncSetAttribute(vproj_kernel,
                         cudaFuncAttributeMaxDynamicSharedMemorySize, GEMM_SMEM);
    cudaFuncSetAttribute(pv_big_kernel,
                         cudaFuncAttributeMaxDynamicSharedMemorySize, PVB_SMEM);

    cvt_all_kernel<<<16896, 256>>>(x, Wv, Wq, Wk);
    qkproj_mma_kernel<<<dim3(32, 1, 8), 256, GEMM_SMEM>>>();
    qk_mma_kernel<<<dim3(32, 32, 8), 256, QK_SMEM>>>();
    rsum_kernel<<<128, 256>>>(gamma);
    vproj_kernel<<<dim3(32, 4, 8), 256, GEMM_SMEM>>>();
    pv_big_kernel<<<dim3(16, 4, 8), 512, PVB_SMEM>>>(out, x);
}

// round 15
// speedup vs baseline: 1.1698x; 1.1698x over previous
#include <cuda_runtime.h>
#include <cuda_bf16.h>
#include <cuda_fp16.h>
#include <cstdint>

#define BB 8
#define CC 512
#define NN 4096
#define DD 64

// ---------------- scratch ----------------------------------------------------
__device__ __nv_bfloat16 g_attn[(long)BB * NN * NN];     // 256 MB attn[n][m] = exp(qk)
__device__ __nv_bfloat16 g_xbf[(long)BB * CC * NN];      // x hi
__device__ __nv_bfloat16 g_xlo[(long)BB * CC * NN];      // x lo
__device__ __nv_bfloat16 g_v[(long)BB * CC * NN];
__device__ __nv_bfloat16 g_Wvbf[CC * CC];
__device__ __nv_bfloat16 g_Wqk2[128 * 1536];             // [d][hW|lW|hW]
__device__ __half g_qt16[(long)BB * NN * DD];            // [b][n][d]
__device__ __half g_k16[(long)BB * DD * NN];             // [b][d][m]
__device__ float g_colpart[(long)BB * 32 * NN];
__device__ float g_colsum[BB * NN];

// ---------------- helpers ----------------------------------------------------
__device__ __forceinline__ float fast_exp(float x) {
    float t = x * 1.4426950408889634f;
    float z = t + 12582912.0f;
    int   n = __float_as_int(z) - 0x4B400000;
    float fi = z - 12582912.0f;
    float f = t - fi;
    float p = 1.3333558e-3f;
    p = fmaf(p, f, 9.6181291e-3f);
    p = fmaf(p, f, 5.5504109e-2f);
    p = fmaf(p, f, 2.4022651e-1f);
    p = fmaf(p, f, 6.9314718e-1f);
    p = fmaf(p, f, 1.0f);
    return p * __int_as_float((n + 127) << 23);
}
__device__ __forceinline__ void ldsm_x4(unsigned r[4], uint32_t a) {
    asm volatile("ldmatrix.sync.aligned.m8n8.x4.shared.b16 {%0,%1,%2,%3}, [%4];"
                 : "=r"(r[0]), "=r"(r[1]), "=r"(r[2]), "=r"(r[3]) : "r"(a));
}
__device__ __forceinline__ void ldsm_x4t(unsigned r[4], uint32_t a) {
    asm volatile("ldmatrix.sync.aligned.m8n8.x4.trans.shared.b16 {%0,%1,%2,%3}, [%4];"
                 : "=r"(r[0]), "=r"(r[1]), "=r"(r[2]), "=r"(r[3]) : "r"(a));
}
__device__ __forceinline__ void mma_bf16(float c[4], const unsigned a[4], const unsigned b2[2]) {
    asm volatile("mma.sync.aligned.m16n8k16.row.col.f32.bf16.bf16.f32 "
                 "{%0,%1,%2,%3},{%4,%5,%6,%7},{%8,%9},{%0,%1,%2,%3};"
                 : "+f"(c[0]), "+f"(c[1]), "+f"(c[2]), "+f"(c[3])
                 : "r"(a[0]), "r"(a[1]), "r"(a[2]), "r"(a[3]), "r"(b2[0]), "r"(b2[1]));
}
__device__ __forceinline__ void mma_f16(float c[4], const unsigned a[4], const unsigned b2[2]) {
    asm volatile("mma.sync.aligned.m16n8k16.row.col.f32.f16.f16.f32 "
                 "{%0,%1,%2,%3},{%4,%5,%6,%7},{%8,%9},{%0,%1,%2,%3};"
                 : "+f"(c[0]), "+f"(c[1]), "+f"(c[2]), "+f"(c[3])
                 : "r"(a[0]), "r"(a[1]), "r"(a[2]), "r"(a[3]), "r"(b2[0]), "r"(b2[1]));
}
__device__ __forceinline__ void cp16(uint32_t s, const void* g) {
    asm volatile("cp.async.cg.shared.global [%0], [%1], 16;" :: "r"(s), "l"(g));
}
__device__ __forceinline__ uint32_t smem_u32(const void* p) {
    return (uint32_t)__cvta_generic_to_shared(p);
}

// ---------------- merged converts --------------------------------------------
__global__ void cvt_all_kernel(const float* __restrict__ x, const float* __restrict__ Wv,
                               const float* __restrict__ Wq, const float* __restrict__ Wk) {
    int bid = blockIdx.x;
    int tid = threadIdx.x;
    if (bid < 16384) {
        long i = ((long)bid * 256 + tid) * 4;
        float4 v = *(const float4*)(x + i);
        float h0 = __bfloat162float(__float2bfloat16(v.x));
        float h1 = __bfloat162float(__float2bfloat16(v.y));
        float h2 = __bfloat162float(__float2bfloat16(v.z));
        float h3 = __bfloat162float(__float2bfloat16(v.w));
        *(__nv_bfloat162*)(g_xbf + i)     = __floats2bfloat162_rn(h0, h1);
        *(__nv_bfloat162*)(g_xbf + i + 2) = __floats2bfloat162_rn(h2, h3);
        *(__nv_bfloat162*)(g_xlo + i)     = __floats2bfloat162_rn(v.x - h0, v.y - h1);
        *(__nv_bfloat162*)(g_xlo + i + 2) = __floats2bfloat162_rn(v.z - h2, v.w - h3);
    } else if (bid < 16640) {
        long i = ((long)(bid - 16384) * 256 + tid) * 4;
        float4 v = *(const float4*)(Wv + i);
        *(__nv_bfloat162*)(g_Wvbf + i)     = __floats2bfloat162_rn(v.x, v.y);
        *(__nv_bfloat162*)(g_Wvbf + i + 2) = __floats2bfloat162_rn(v.z, v.w);
    } else {
        int i = (bid - 16640) * 256 + tid;
        int d = i >> 9, c = i & 511;
        float v = (d < 64) ? Wq[d * 512 + c] : Wk[(d - 64) * 512 + c];
        __nv_bfloat16 h = __float2bfloat16(v);
        __nv_bfloat16 l = __float2bfloat16(v - __bfloat162float(h));
        g_Wqk2[d * 1536 + c] = h;
        g_Wqk2[d * 1536 + 512 + c] = l;
        g_Wqk2[d * 1536 + 1024 + c] = h;
    }
}

// ---------------- qk projection (bf16 split GEMM K=1536), R13 2-stage --------
// k rows (d>=64) -> g_k16 [d][m] fp16 direct; q rows (d<64) -> smem transpose
// -> g_qt16 [n][d] fp16 coalesced.
__global__ __launch_bounds__(256, 2)
void qkproj_mma_kernel() {
    constexpr int NIT = 48;
    __shared__ __align__(16) __nv_bfloat16 As[2 * 128 * 40];
    __shared__ __align__(16) __nv_bfloat16 Bs[2 * 32 * 136];
    __shared__ __align__(16) __half tq[128 * 68];    // [n-local][d], stride 68
    int b = blockIdx.z;
    int nbase = blockIdx.x * 128;
    int tid = threadIdx.x, lane = tid & 31, warp = tid >> 5;
    int wm = warp & 3, wn = warp >> 2;
    const __nv_bfloat16* xh = g_xbf + (long)b * CC * NN;
    const __nv_bfloat16* xl = g_xlo + (long)b * CC * NN;

    float acc[2][8][4];
#pragma unroll
    for (int t = 0; t < 2; t++)
#pragma unroll
        for (int j = 0; j < 8; j++)
#pragma unroll
            for (int e = 0; e < 4; e++) acc[t][j][e] = 0.f;

    uint32_t as0 = smem_u32(As), bs0 = smem_u32(Bs);
    uint32_t a_st = ((tid >> 2) * 40 + (tid & 3) * 8) * 2;
    uint32_t b_st = ((tid >> 4) * 136 + (tid & 15) * 8) * 2;
    const long a_g0 = (long)(tid >> 2) * 1536 + (tid & 3) * 8;
    const long b_g0 = (long)(tid >> 4) * NN + nbase + (tid & 15) * 8;
    uint32_t a_off = ((wm * 32 + (lane & 15)) * 40 + (lane >> 4) * 8) * 2;
    uint32_t b_off = ((lane & 15) * 136 + wn * 64 + (lane >> 4) * 8) * 2;

    auto issue = [&](int c, int st) {
        uint32_t ab = as0 + st * 10240, bb = bs0 + st * 8704;
        cp16(ab + a_st, g_Wqk2 + a_g0 + c * 32);
        cp16(ab + a_st + 64 * 80, g_Wqk2 + a_g0 + 64L * 1536 + c * 32);
        const __nv_bfloat16* Bsrc =
            (c < 16) ? (xh + (long)(c * 32) * NN)
                     : (c < 32) ? (xh + (long)((c - 16) * 32) * NN)
                                : (xl + (long)((c - 32) * 32) * NN);
        cp16(bb + b_st, Bsrc + b_g0);
        cp16(bb + b_st + 16 * 272, Bsrc + b_g0 + 16L * NN);
        asm volatile("cp.async.commit_group;" ::);
    };

    issue(0, 0);
    for (int it = 0; it < NIT; it++) {
        if (it + 1 < NIT) {
            issue(it + 1, (it + 1) & 1);
            asm volatile("cp.async.wait_group 1;" ::);
        } else {
            asm volatile("cp.async.wait_group 0;" ::);
        }
        __syncthreads();
        uint32_t aa = as0 + (it & 1) * 10240 + a_off;
        uint32_t bb2 = bs0 + (it & 1) * 8704 + b_off;
#pragma unroll
        for (int ks = 0; ks < 2; ks++) {
            unsigned af[2][4];
            ldsm_x4(af[0], aa + ks * 32);
            ldsm_x4(af[1], aa + 1280 + ks * 32);
#pragma unroll
            for (int jp = 0; jp < 4; jp++) {
                unsigned bf[4];
                ldsm_x4t(bf, bb2 + jp * 32 + ks * 4352);
                mma_bf16(acc[0][2 * jp],     af[0], bf);
                mma_bf16(acc[0][2 * jp + 1], af[0], bf + 2);
                mma_bf16(acc[1][2 * jp],     af[1], bf);
                mma_bf16(acc[1][2 * jp + 1], af[1], bf + 2);
            }
        }
        __syncthreads();
    }

    int row0 = wm * 32 + (lane >> 2);
    int col0l = wn * 64 + (lane & 3) * 2;   // local n
#pragma unroll
    for (int t = 0; t < 2; t++)
#pragma unroll
        for (int rr = 0; rr < 2; rr++) {
            int d = row0 + t * 16 + rr * 8;
            if (d < 64) {
#pragma unroll
                for (int j = 0; j < 8; j++) {
                    int c = col0l + j * 8;
                    tq[c * 68 + d]       = __float2half(acc[t][j][rr * 2]);
                    tq[(c + 1) * 68 + d] = __float2half(acc[t][j][rr * 2 + 1]);
                }
            } else {
                __half* dst = g_k16 + ((long)b * DD + d - 64) * NN + nbase;
#pragma unroll
                for (int j = 0; j < 8; j++) {
                    *(__half2*)(dst + col0l + j * 8) =
                        __floats2half2_rn(acc[t][j][rr * 2], acc[t][j][rr * 2 + 1]);
                }
            }
        }
    __syncthreads();
    {
        int n = tid >> 1, dh = (tid & 1) * 32;
        __half* dst = g_qt16 + (long)b * NN * DD + (long)(nbase + n) * DD + dh;
        const __half* src = tq + n * 68 + dh;
#pragma unroll
        for (int c4 = 0; c4 < 8; c4++)
            *(uint2*)(dst + c4 * 4) = *(const uint2*)(src + c4 * 4);
    }
}

// ---------------- qk fp16 GEMM (K=64) + exp + smem-staged attn store ---------
__global__ __launch_bounds__(256, 2)
void qk_mma_kernel() {
    constexpr int KD = 64;
    constexpr int CTS = 136;
    extern __shared__ __align__(16) char qsm[];
    __half* As = (__half*)qsm;
    __half* Bs = (__half*)(qsm + 20480);
    __nv_bfloat16* Ct = (__nv_bfloat16*)qsm;
    __shared__ float cred[4 * 128];
    int b = blockIdx.z;
    const __half* A  = g_qt16 + (long)b * NN * KD;
    const __half* Bm = g_k16  + (long)b * KD * NN;
    int mbase = blockIdx.y * 128;
    int nbase = blockIdx.x * 128;
    int tid = threadIdx.x, lane = tid & 31, warp = tid >> 5;
    int wm = warp & 3, wn = warp >> 2;

    float acc[2][8][4];
#pragma unroll
    for (int t = 0; t < 2; t++)
#pragma unroll
        for (int j = 0; j < 8; j++)
#pragma unroll
            for (int e = 0; e < 4; e++) acc[t][j][e] = 0.f;

    uint32_t as0 = smem_u32(As), bs0 = smem_u32(Bs);
    uint32_t a_st = ((tid >> 2) * 40 + (tid & 3) * 8) * 2;
    uint32_t b_st = ((tid >> 4) * 136 + (tid & 15) * 8) * 2;
    const long a_g0 = (long)(mbase + (tid >> 2)) * KD + (tid & 3) * 8;
    const long b_g0 = (long)(tid >> 4) * NN + nbase + (tid & 15) * 8;
    uint32_t a_off = ((wm * 32 + (lane & 15)) * 40 + (lane >> 4) * 8) * 2;
    uint32_t b_off = ((lane & 15) * 136 + wn * 64 + (lane >> 4) * 8) * 2;

#define QK_ISSUE(k0, st)                                                        \
    {                                                                           \
        uint32_t ab = as0 + (st) * 10240, bb = bs0 + (st) * 8704;               \
        cp16(ab + a_st, A + a_g0 + (k0));                                       \
        cp16(ab + a_st + 64 * 80, A + a_g0 + 64L * KD + (k0));                  \
        cp16(bb + b_st, Bm + b_g0 + (long)(k0) * NN);                           \
        cp16(bb + b_st + 16 * 272, Bm + b_g0 + (long)((k0) + 16) * NN);         \
        asm volatile("cp.async.commit_group;" ::);                              \
    }

    QK_ISSUE(0, 0);
    QK_ISSUE(32, 1);
#pragma unroll
    for (int it = 0; it < 2; it++) {
        if (it == 0) {
            asm volatile("cp.async.wait_group 1;" ::);
        } else {
            asm volatile("cp.async.wait_group 0;" ::);
        }
        __syncthreads();
        uint32_t aa = as0 + it * 10240 + a_off;
        uint32_t bbq = bs0 + it * 8704 + b_off;
#pragma unroll
        for (int ks = 0; ks < 2; ks++) {
            unsigned af[2][4];
            ldsm_x4(af[0], aa + ks * 32);
            ldsm_x4(af[1], aa + 1280 + ks * 32);
#pragma unroll
            for (int jp = 0; jp < 4; jp++) {
                unsigned bf[4];
                ldsm_x4t(bf, bbq + jp * 32 + ks * 4352);
                mma_f16(acc[0][2 * jp],     af[0], bf);
                mma_f16(acc[0][2 * jp + 1], af[0], bf + 2);
                mma_f16(acc[1][2 * jp],     af[1], bf);
                mma_f16(acc[1][2 * jp + 1], af[1], bf + 2);
            }
        }
    }
#undef QK_ISSUE

    __syncthreads();

    int row0l = wm * 32 + (lane >> 2);
    int col0l = wn * 64 + (lane & 3) * 2;
    float colp[8][2];
#pragma unroll
    for (int j = 0; j < 8; j++) { colp[j][0] = 0.f; colp[j][1] = 0.f; }
#pragma unroll
    for (int t = 0; t < 2; t++)
#pragma unroll
        for (int j = 0; j < 8; j++) {
            float e0 = fast_exp(acc[t][j][0]);
            float e1 = fast_exp(acc[t][j][1]);
            float e2 = fast_exp(acc[t][j][2]);
            float e3 = fast_exp(acc[t][j][3]);
            colp[j][0] += e0 + e2;
            colp[j][1] += e1 + e3;
            int r = row0l + t * 16, c = col0l + j * 8;
            *(__nv_bfloat162*)(Ct + r * CTS + c)       = __floats2bfloat162_rn(e0, e1);
            *(__nv_bfloat162*)(Ct + (r + 8) * CTS + c) = __floats2bfloat162_rn(e2, e3);
        }
#pragma unroll
    for (int off = 16; off >= 4; off >>= 1)
#pragma unroll
        for (int j = 0; j < 8; j++) {
            colp[j][0] += __shfl_xor_sync(0xffffffffu, colp[j][0], off);
            colp[j][1] += __shfl_xor_sync(0xffffffffu, colp[j][1], off);
        }
    if ((lane >> 2) == 0) {
#pragma unroll
        for (int j = 0; j < 8; j++) {
            cred[wm * 128 + wn * 64 + j * 8 + (lane & 3) * 2]     = colp[j][0];
            cred[wm * 128 + wn * 64 + j * 8 + (lane & 3) * 2 + 1] = colp[j][1];
        }
    }
    __syncthreads();

    __nv_bfloat16* ab = g_attn + ((long)b << 24);
    {
        int row = tid >> 1;
        int half = tid & 1;
        const __nv_bfloat16* src = Ct + row * CTS;
        __nv_bfloat16* dstg = ab + (long)(mbase + row) * NN + nbase;
#pragma unroll
        for (int j2 = 0; j2 < 8; j2++) {
            int cchunk = (half + 2 * j2) * 8;
            *(uint4*)(dstg + cchunk) = *(const uint4*)(src + cchunk);
        }
    }
    if (tid < 128) {
        float s = cred[tid] + cred[128 + tid] + cred[256 + tid] + cred[384 + tid];
        g_colpart[((long)b * 32 + blockIdx.y) * NN + nbase + tid] = s;
    }
}

// ---------------- bf16 tensor GEMM (v-proj / PV), R13 4-stage paired-iter ----
// RSUM template flag: when true, grid.y has one extra stripe (y==YDIM) whose
// blocks ONLY run the colsum finalize (independent of the GEMM blocks; its
// output is consumed by the NEXT kernel launch, so no intra-grid ordering
// is needed).
template <int KDIM, bool PV, bool RSUM>
__global__ __launch_bounds__(256)
void mma_gemm_kernel(float* __restrict__ Out, const float* __restrict__ Xres,
                     const float* __restrict__ gamma) {
    constexpr int NIT = KDIM / 32;
    if (RSUM && blockIdx.y == 4) {
        int idx = (blockIdx.x + 32 * blockIdx.z) * 256 + threadIdx.x;  // 0..65535
        if (idx < 32768) {
            int b = idx >> 12, col = idx & 4095;
            const float* p = g_colpart + (long)b * 32 * NN + col;
            float s = 0.f;
#pragma unroll
            for (int t = 0; t < 32; t++) s += p[(long)t * NN];
            g_colsum[idx] = gamma[0] / s;
        }
        return;
    }
    extern __shared__ __align__(16) char dsm[];
    __nv_bfloat16* As = (__nv_bfloat16*)dsm;       // 4 * 5120 bf16
    __nv_bfloat16* Bs = As + 4 * 5120;             // 4 * 4352 bf16
    int b = blockIdx.z;
    const __nv_bfloat16* A  = PV ? (g_v + (long)b * CC * NN) : g_Wvbf;
    const __nv_bfloat16* Bm = PV ? (g_attn + ((long)b << 24)) : (g_xbf + (long)b * CC * NN);
    int mbase = blockIdx.y * 128, nbase = blockIdx.x * 128;
    int tid = threadIdx.x, lane = tid & 31, warp = tid >> 5;
    int wm = warp & 3, wn = warp >> 2;

    float acc[2][8][4];
#pragma unroll
    for (int t = 0; t < 2; t++)
#pragma unroll
        for (int j = 0; j < 8; j++)
#pragma unroll
            for (int e = 0; e < 4; e++) acc[t][j][e] = 0.f;

    uint32_t as0 = smem_u32(As), bs0 = smem_u32(Bs);
    uint32_t a_st = ((tid >> 2) * 40 + (tid & 3) * 8) * 2;
    uint32_t b_st = ((tid >> 4) * 136 + (tid & 15) * 8) * 2;
    const long a_g0 = (long)(mbase + (tid >> 2)) * KDIM + (tid & 3) * 8;
    const long b_g0 = (long)(tid >> 4) * NN + nbase + (tid & 15) * 8;
    uint32_t a_off = ((wm * 32 + (lane & 15)) * 40 + (lane >> 4) * 8) * 2;
    uint32_t b_off = ((lane & 15) * 136 + wn * 64 + (lane >> 4) * 8) * 2;

#define GM_ISSUE(k0, st)                                                        \
    {                                                                           \
        uint32_t ab = as0 + (st) * 10240, bb = bs0 + (st) * 8704;               \
        cp16(ab + a_st, A + a_g0 + (k0));                                       \
        cp16(ab + a_st + 64 * 80, A + a_g0 + 64L * KDIM + (k0));                \
        cp16(bb + b_st, Bm + b_g0 + (long)(k0) * NN);                           \
        cp16(bb + b_st + 16 * 272, Bm + b_g0 + (long)((k0) + 16) * NN);         \
        asm volatile("cp.async.commit_group;" ::);                              \
    }

    auto compute_stage = [&](int st) {
        uint32_t aa = as0 + st * 10240 + a_off;
        uint32_t bb2 = bs0 + st * 8704 + b_off;
#pragma unroll
        for (int ks = 0; ks < 2; ks++) {
            unsigned af[2][4];
            ldsm_x4(af[0], aa + ks * 32);
            ldsm_x4(af[1], aa + 1280 + ks * 32);
#pragma unroll
            for (int jp = 0; jp < 4; jp++) {
                unsigned bf[4];
                ldsm_x4t(bf, bb2 + jp * 32 + ks * 4352);
                mma_bf16(acc[0][2 * jp],     af[0], bf);
                mma_bf16(acc[0][2 * jp + 1], af[0], bf + 2);
                mma_bf16(acc[1][2 * jp],     af[1], bf);
                mma_bf16(acc[1][2 * jp + 1], af[1], bf + 2);
            }
        }
    };

    GM_ISSUE(0, 0);
    GM_ISSUE(32, 1);
    for (int it = 0; it < NIT; it += 2) {
        if (it + 2 < NIT) {
            GM_ISSUE((it + 2) * 32, (it + 2) & 3);
            GM_ISSUE((it + 3) * 32, (it + 3) & 3);
            asm volatile("cp.async.wait_group 2;" ::);
        } else {
            asm volatile("cp.async.wait_group 0;" ::);
        }
        __syncthreads();
        compute_stage(it & 3);
        compute_stage((it + 1) & 3);
        __syncthreads();
    }
#undef GM_ISSUE

    int row0 = mbase + wm * 32 + (lane >> 2);
    int col0 = nbase + wn * 64 + (lane & 3) * 2;
    if (!PV) {
        __nv_bfloat16* Vb = g_v + (long)b * CC * NN;
#pragma unroll
        for (int t = 0; t < 2; t++)
#pragma unroll
            for (int j = 0; j < 8; j++) {
                int r = row0 + t * 16, c = col0 + j * 8;
                *(__nv_bfloat162*)(Vb + (long)r * NN + c) =
                    __floats2bfloat162_rn(acc[t][j][0], acc[t][j][1]);
                *(__nv_bfloat162*)(Vb + (long)(r + 8) * NN + c) =
                    __floats2bfloat162_rn(acc[t][j][2], acc[t][j][3]);
            }
    } else {
        float* Ob = Out + (long)b * CC * NN;
        const float* Xb = Xres + (long)b * CC * NN;
        const float* rs = g_colsum + b * NN;
#pragma unroll
        for (int j = 0; j < 8; j++) {
            int c = col0 + j * 8;
            float r0 = rs[c], r1 = rs[c + 1];
#pragma unroll
            for (int t = 0; t < 2; t++) {
                int r = row0 + t * 16;
                float2 x0 = *(const float2*)(Xb + (long)r * NN + c);
                float2 o0 = {fmaf(acc[t][j][0], r0, x0.x), fmaf(acc[t][j][1], r1, x0.y)};
                *(float2*)(Ob + (long)r * NN + c) = o0;
                float2 x1 = *(const float2*)(Xb + (long)(r + 8) * NN + c);
                float2 o1 = {fmaf(acc[t][j][2], r0, x1.x), fmaf(acc[t][j][3], r1, x1.y)};
                *(float2*)(Ob + (long)(r + 8) * NN + c) = o1;
            }
        }
    }
}

// ---------------- launch -----------------------------------------------------
extern "C" void kernel_launch(void* const* d_in, const int* in_sizes, int n_in,
                              void* d_out, int out_size) {
    const float* x     = (const float*)d_in[0];
    const float* Wq    = (const float*)d_in[1];
    const float* Wk    = (const float*)d_in[2];
    const float* Wv    = (const float*)d_in[3];
    const float* gamma = (const float*)d_in[4];
    float* out = (float*)d_out;

    const int GEMM_SMEM = 4 * (10240 + 8704);  // 75776 bytes
    const int QK_SMEM   = 20480 + 17408;       // 37888 bytes (Ct needs 34816)
    cudaFuncSetAttribute(mma_gemm_kernel<512, false, true>,
                         cudaFuncAttributeMaxDynamicSharedMemorySize, GEMM_SMEM);
    cudaFuncSetAttribute(mma_gemm_kernel<4096, true, false>,
                         cudaFuncAttributeMaxDynamicSharedMemorySize, GEMM_SMEM);

    cvt_all_kernel<<<16896, 256>>>(x, Wv, Wq, Wk);
    qkproj_mma_kernel<<<dim3(32, 1, 8), 256>>>();
    qk_mma_kernel<<<dim3(32, 32, 8), 256, QK_SMEM>>>();
    // v-proj GEMM + rsum folded in as the y==4 block stripe
    mma_gemm_kernel<512, false, true><<<dim3(32, 5, 8), 256, GEMM_SMEM>>>(nullptr, nullptr, gamma);
    mma_gemm_kernel<4096, true, false><<<dim3(32, 4, 8), 256, GEMM_SMEM>>>(out, x, nullptr);
}

// round 16
// speedup vs baseline: 1.2330x; 1.0540x over previous
#include <cuda_runtime.h>
#include <cuda_bf16.h>
#include <cuda_fp16.h>
#include <cstdint>

#define BB 8
#define CC 512
#define NN 4096
#define DD 64

// ---------------- scratch ----------------------------------------------------
__device__ __nv_bfloat16 g_attn[(long)BB * NN * NN];     // 256 MB attn[n][m] = exp(qk)
__device__ __nv_bfloat16 g_xbf[(long)BB * CC * NN];      // x hi
__device__ __nv_bfloat16 g_v[(long)BB * CC * NN];
__device__ __nv_bfloat16 g_Wvbf[CC * CC];
__device__ __nv_bfloat16 g_Wqk2[128 * 1024];             // [d][hW|lW]
__device__ __half g_qt16[(long)BB * NN * DD];            // [b][n][d]
__device__ __half g_k16[(long)BB * DD * NN];             // [b][d][m]
__device__ float g_colpart[(long)BB * 32 * NN];
__device__ float g_colsum[BB * NN];

// ---------------- helpers ----------------------------------------------------
__device__ __forceinline__ void ldsm_x4(unsigned r[4], uint32_t a) {
    asm volatile("ldmatrix.sync.aligned.m8n8.x4.shared.b16 {%0,%1,%2,%3}, [%4];"
                 : "=r"(r[0]), "=r"(r[1]), "=r"(r[2]), "=r"(r[3]) : "r"(a));
}
__device__ __forceinline__ void ldsm_x4t(unsigned r[4], uint32_t a) {
    asm volatile("ldmatrix.sync.aligned.m8n8.x4.trans.shared.b16 {%0,%1,%2,%3}, [%4];"
                 : "=r"(r[0]), "=r"(r[1]), "=r"(r[2]), "=r"(r[3]) : "r"(a));
}
__device__ __forceinline__ void mma_bf16(float c[4], const unsigned a[4], const unsigned b2[2]) {
    asm volatile("mma.sync.aligned.m16n8k16.row.col.f32.bf16.bf16.f32 "
                 "{%0,%1,%2,%3},{%4,%5,%6,%7},{%8,%9},{%0,%1,%2,%3};"
                 : "+f"(c[0]), "+f"(c[1]), "+f"(c[2]), "+f"(c[3])
                 : "r"(a[0]), "r"(a[1]), "r"(a[2]), "r"(a[3]), "r"(b2[0]), "r"(b2[1]));
}
__device__ __forceinline__ void mma_f16(float c[4], const unsigned a[4], const unsigned b2[2]) {
    asm volatile("mma.sync.aligned.m16n8k16.row.col.f32.f16.f16.f32 "
                 "{%0,%1,%2,%3},{%4,%5,%6,%7},{%8,%9},{%0,%1,%2,%3};"
                 : "+f"(c[0]), "+f"(c[1]), "+f"(c[2]), "+f"(c[3])
                 : "r"(a[0]), "r"(a[1]), "r"(a[2]), "r"(a[3]), "r"(b2[0]), "r"(b2[1]));
}
__device__ __forceinline__ void cp16(uint32_t s, const void* g) {
    asm volatile("cp.async.cg.shared.global [%0], [%1], 16;" :: "r"(s), "l"(g));
}
__device__ __forceinline__ uint32_t smem_u32(const void* p) {
    return (uint32_t)__cvta_generic_to_shared(p);
}

// ---------------- merged converts --------------------------------------------
__global__ void cvt_all_kernel(const float* __restrict__ x, const float* __restrict__ Wv,
                               const float* __restrict__ Wq, const float* __restrict__ Wk) {
    int bid = blockIdx.x;
    int tid = threadIdx.x;
    if (bid < 16384) {
        long i = ((long)bid * 256 + tid) * 4;
        float4 v = *(const float4*)(x + i);
        *(__nv_bfloat162*)(g_xbf + i)     = __floats2bfloat162_rn(v.x, v.y);
        *(__nv_bfloat162*)(g_xbf + i + 2) = __floats2bfloat162_rn(v.z, v.w);
    } else if (bid < 16640) {
        long i = ((long)(bid - 16384) * 256 + tid) * 4;
        float4 v = *(const float4*)(Wv + i);
        *(__nv_bfloat162*)(g_Wvbf + i)     = __floats2bfloat162_rn(v.x, v.y);
        *(__nv_bfloat162*)(g_Wvbf + i + 2) = __floats2bfloat162_rn(v.z, v.w);
    } else {
        int i = (bid - 16640) * 256 + tid;
        int d = i >> 9, c = i & 511;
        float v = (d < 64) ? Wq[d * 512 + c] : Wk[(d - 64) * 512 + c];
        __nv_bfloat16 h = __float2bfloat16(v);
        __nv_bfloat16 l = __float2bfloat16(v - __bfloat162float(h));
        g_Wqk2[d * 1024 + c] = h;
        g_Wqk2[d * 1024 + 512 + c] = l;
    }
}

// ---------------- qk projection (2-term split GEMM K=1024), R13 2-stage ------
// D = hW·hx + lW·hx = W·hx (exact to fp32). k rows -> g_k16; q rows -> smem
// transpose -> g_qt16.
__global__ __launch_bounds__(256, 2)
void qkproj_mma_kernel() {
    constexpr int NIT = 32;
    __shared__ __align__(16) __nv_bfloat16 As[2 * 128 * 40];
    __shared__ __align__(16) __nv_bfloat16 Bs[2 * 32 * 136];
    __shared__ __align__(16) __half tq[128 * 68];    // [n-local][d], stride 68
    int b = blockIdx.z;
    int nbase = blockIdx.x * 128;
    int tid = threadIdx.x, lane = tid & 31, warp = tid >> 5;
    int wm = warp & 3, wn = warp >> 2;
    const __nv_bfloat16* xh = g_xbf + (long)b * CC * NN;

    float acc[2][8][4];
#pragma unroll
    for (int t = 0; t < 2; t++)
#pragma unroll
        for (int j = 0; j < 8; j++)
#pragma unroll
            for (int e = 0; e < 4; e++) acc[t][j][e] = 0.f;

    uint32_t as0 = smem_u32(As), bs0 = smem_u32(Bs);
    uint32_t a_st = ((tid >> 2) * 40 + (tid & 3) * 8) * 2;
    uint32_t b_st = ((tid >> 4) * 136 + (tid & 15) * 8) * 2;
    const long a_g0 = (long)(tid >> 2) * 1024 + (tid & 3) * 8;
    const long b_g0 = (long)(tid >> 4) * NN + nbase + (tid & 15) * 8;
    uint32_t a_off = ((wm * 32 + (lane & 15)) * 40 + (lane >> 4) * 8) * 2;
    uint32_t b_off = ((lane & 15) * 136 + wn * 64 + (lane >> 4) * 8) * 2;

    auto issue = [&](int c, int st) {
        uint32_t ab = as0 + st * 10240, bb = bs0 + st * 8704;
        cp16(ab + a_st, g_Wqk2 + a_g0 + c * 32);
        cp16(ab + a_st + 64 * 80, g_Wqk2 + a_g0 + 64L * 1024 + c * 32);
        // both K-halves read hx: rows (c & 15) * 32
        const __nv_bfloat16* Bsrc = xh + (long)((c & 15) * 32) * NN;
        cp16(bb + b_st, Bsrc + b_g0);
        cp16(bb + b_st + 16 * 272, Bsrc + b_g0 + 16L * NN);
        asm volatile("cp.async.commit_group;" ::);
    };

    issue(0, 0);
    for (int it = 0; it < NIT; it++) {
        if (it + 1 < NIT) {
            issue(it + 1, (it + 1) & 1);
            asm volatile("cp.async.wait_group 1;" ::);
        } else {
            asm volatile("cp.async.wait_group 0;" ::);
        }
        __syncthreads();
        uint32_t aa = as0 + (it & 1) * 10240 + a_off;
        uint32_t bb2 = bs0 + (it & 1) * 8704 + b_off;
#pragma unroll
        for (int ks = 0; ks < 2; ks++) {
            unsigned af[2][4];
            ldsm_x4(af[0], aa + ks * 32);
            ldsm_x4(af[1], aa + 1280 + ks * 32);
#pragma unroll
            for (int jp = 0; jp < 4; jp++) {
                unsigned bf[4];
                ldsm_x4t(bf, bb2 + jp * 32 + ks * 4352);
                mma_bf16(acc[0][2 * jp],     af[0], bf);
                mma_bf16(acc[0][2 * jp + 1], af[0], bf + 2);
                mma_bf16(acc[1][2 * jp],     af[1], bf);
                mma_bf16(acc[1][2 * jp + 1], af[1], bf + 2);
            }
        }
        __syncthreads();
    }

    int row0 = wm * 32 + (lane >> 2);
    int col0l = wn * 64 + (lane & 3) * 2;   // local n
#pragma unroll
    for (int t = 0; t < 2; t++)
#pragma unroll
        for (int rr = 0; rr < 2; rr++) {
            int d = row0 + t * 16 + rr * 8;
            if (d < 64) {
#pragma unroll
                for (int j = 0; j < 8; j++) {
                    int c = col0l + j * 8;
                    tq[c * 68 + d]       = __float2half(acc[t][j][rr * 2]);
                    tq[(c + 1) * 68 + d] = __float2half(acc[t][j][rr * 2 + 1]);
                }
            } else {
                __half* dst = g_k16 + ((long)b * DD + d - 64) * NN + nbase;
#pragma unroll
                for (int j = 0; j < 8; j++) {
                    *(__half2*)(dst + col0l + j * 8) =
                        __floats2half2_rn(acc[t][j][rr * 2], acc[t][j][rr * 2 + 1]);
                }
            }
        }
    __syncthreads();
    {
        int n = tid >> 1, dh = (tid & 1) * 32;
        __half* dst = g_qt16 + (long)b * NN * DD + (long)(nbase + n) * DD + dh;
        const __half* src = tq + n * 68 + dh;
#pragma unroll
        for (int c4 = 0; c4 < 8; c4++)
            *(uint2*)(dst + c4 * 4) = *(const uint2*)(src + c4 * 4);
    }
}

// ---------------- qk fp16 GEMM (K=64) + MUFU exp + smem-staged attn store ----
__global__ __launch_bounds__(256, 2)
void qk_mma_kernel() {
    constexpr int KD = 64;
    constexpr int CTS = 136;
    extern __shared__ __align__(16) char qsm[];
    __half* As = (__half*)qsm;
    __half* Bs = (__half*)(qsm + 20480);
    __nv_bfloat16* Ct = (__nv_bfloat16*)qsm;
    __shared__ float cred[4 * 128];
    int b = blockIdx.z;
    const __half* A  = g_qt16 + (long)b * NN * KD;
    const __half* Bm = g_k16  + (long)b * KD * NN;
    int mbase = blockIdx.y * 128;
    int nbase = blockIdx.x * 128;
    int tid = threadIdx.x, lane = tid & 31, warp = tid >> 5;
    int wm = warp & 3, wn = warp >> 2;

    float acc[2][8][4];
#pragma unroll
    for (int t = 0; t < 2; t++)
#pragma unroll
        for (int j = 0; j < 8; j++)
#pragma unroll
            for (int e = 0; e < 4; e++) acc[t][j][e] = 0.f;

    uint32_t as0 = smem_u32(As), bs0 = smem_u32(Bs);
    uint32_t a_st = ((tid >> 2) * 40 + (tid & 3) * 8) * 2;
    uint32_t b_st = ((tid >> 4) * 136 + (tid & 15) * 8) * 2;
    const long a_g0 = (long)(mbase + (tid >> 2)) * KD + (tid & 3) * 8;
    const long b_g0 = (long)(tid >> 4) * NN + nbase + (tid & 15) * 8;
    uint32_t a_off = ((wm * 32 + (lane & 15)) * 40 + (lane >> 4) * 8) * 2;
    uint32_t b_off = ((lane & 15) * 136 + wn * 64 + (lane >> 4) * 8) * 2;

#define QK_ISSUE(k0, st)                                                        \
    {                                                                           \
        uint32_t ab = as0 + (st) * 10240, bb = bs0 + (st) * 8704;               \
        cp16(ab + a_st, A + a_g0 + (k0));                                       \
        cp16(ab + a_st + 64 * 80, A + a_g0 + 64L * KD + (k0));                  \
        cp16(bb + b_st, Bm + b_g0 + (long)(k0) * NN);                           \
        cp16(bb + b_st + 16 * 272, Bm + b_g0 + (long)((k0) + 16) * NN);         \
        asm volatile("cp.async.commit_group;" ::);                              \
    }

    QK_ISSUE(0, 0);
    QK_ISSUE(32, 1);
#pragma unroll
    for (int it = 0; it < 2; it++) {
        if (it == 0) {
            asm volatile("cp.async.wait_group 1;" ::);
        } else {
            asm volatile("cp.async.wait_group 0;" ::);
        }
        __syncthreads();
        uint32_t aa = as0 + it * 10240 + a_off;
        uint32_t bbq = bs0 + it * 8704 + b_off;
#pragma unroll
        for (int ks = 0; ks < 2; ks++) {
            unsigned af[2][4];
            ldsm_x4(af[0], aa + ks * 32);
            ldsm_x4(af[1], aa + 1280 + ks * 32);
#pragma unroll
            for (int jp = 0; jp < 4; jp++) {
                unsigned bf[4];
                ldsm_x4t(bf, bbq + jp * 32 + ks * 4352);
                mma_f16(acc[0][2 * jp],     af[0], bf);
                mma_f16(acc[0][2 * jp + 1], af[0], bf + 2);
                mma_f16(acc[1][2 * jp],     af[1], bf);
                mma_f16(acc[1][2 * jp + 1], af[1], bf + 2);
            }
        }
    }
#undef QK_ISSUE

    __syncthreads();

    int row0l = wm * 32 + (lane >> 2);
    int col0l = wn * 64 + (lane & 3) * 2;
    float colp[8][2];
#pragma unroll
    for (int j = 0; j < 8; j++) { colp[j][0] = 0.f; colp[j][1] = 0.f; }
#pragma unroll
    for (int t = 0; t < 2; t++)
#pragma unroll
        for (int j = 0; j < 8; j++) {
            float e0 = __expf(acc[t][j][0]);
            float e1 = __expf(acc[t][j][1]);
            float e2 = __expf(acc[t][j][2]);
            float e3 = __expf(acc[t][j][3]);
            colp[j][0] += e0 + e2;
            colp[j][1] += e1 + e3;
            int r = row0l + t * 16, c = col0l + j * 8;
            *(__nv_bfloat162*)(Ct + r * CTS + c)       = __floats2bfloat162_rn(e0, e1);
            *(__nv_bfloat162*)(Ct + (r + 8) * CTS + c) = __floats2bfloat162_rn(e2, e3);
        }
#pragma unroll
    for (int off = 16; off >= 4; off >>= 1)
#pragma unroll
        for (int j = 0; j < 8; j++) {
            colp[j][0] += __shfl_xor_sync(0xffffffffu, colp[j][0], off);
            colp[j][1] += __shfl_xor_sync(0xffffffffu, colp[j][1], off);
        }
    if ((lane >> 2) == 0) {
#pragma unroll
        for (int j = 0; j < 8; j++) {
            cred[wm * 128 + wn * 64 + j * 8 + (lane & 3) * 2]     = colp[j][0];
            cred[wm * 128 + wn * 64 + j * 8 + (lane & 3) * 2 + 1] = colp[j][1];
        }
    }
    __syncthreads();

    __nv_bfloat16* ab = g_attn + ((long)b << 24);
    {
        int row = tid >> 1;
        int half = tid & 1;
        const __nv_bfloat16* src = Ct + row * CTS;
        __nv_bfloat16* dstg = ab + (long)(mbase + row) * NN + nbase;
#pragma unroll
        for (int j2 = 0; j2 < 8; j2++) {
            int cchunk = (half + 2 * j2) * 8;
            *(uint4*)(dstg + cchunk) = *(const uint4*)(src + cchunk);
        }
    }
    if (tid < 128) {
        float s = cred[tid] + cred[128 + tid] + cred[256 + tid] + cred[384 + tid];
        g_colpart[((long)b * 32 + blockIdx.y) * NN + nbase + tid] = s;
    }
}

// ---------------- bf16 tensor GEMM (v-proj / PV), 4-stage paired-iter --------
// RSUM=true adds a y==4 stripe that only finalizes colsum (independent blocks;
// output consumed by the NEXT launch).
template <int KDIM, bool PV, bool RSUM>
__global__ __launch_bounds__(256)
void mma_gemm_kernel(float* __restrict__ Out, const float* __restrict__ Xres,
                     const float* __restrict__ gamma) {
    constexpr int NIT = KDIM / 32;
    if (RSUM && blockIdx.y == 4) {
        int idx = (blockIdx.x + 32 * blockIdx.z) * 256 + threadIdx.x;
        if (idx < 32768) {
            int b = idx >> 12, col = idx & 4095;
            const float* p = g_colpart + (long)b * 32 * NN + col;
            float s = 0.f;
#pragma unroll
            for (int t = 0; t < 32; t++) s += p[(long)t * NN];
            g_colsum[idx] = gamma[0] / s;
        }
        return;
    }
    extern __shared__ __align__(16) char dsm[];
    __nv_bfloat16* As = (__nv_bfloat16*)dsm;       // 4 * 5120 bf16
    __nv_bfloat16* Bs = As + 4 * 5120;             // 4 * 4352 bf16
    int b = blockIdx.z;
    const __nv_bfloat16* A  = PV ? (g_v + (long)b * CC * NN) : g_Wvbf;
    const __nv_bfloat16* Bm = PV ? (g_attn + ((long)b << 24)) : (g_xbf + (long)b * CC * NN);
    int mbase = blockIdx.y * 128, nbase = blockIdx.x * 128;
    int tid = threadIdx.x, lane = tid & 31, warp = tid >> 5;
    int wm = warp & 3, wn = warp >> 2;

    float acc[2][8][4];
#pragma unroll
    for (int t = 0; t < 2; t++)
#pragma unroll
        for (int j = 0; j < 8; j++)
#pragma unroll
            for (int e = 0; e < 4; e++) acc[t][j][e] = 0.f;

    uint32_t as0 = smem_u32(As), bs0 = smem_u32(Bs);
    uint32_t a_st = ((tid >> 2) * 40 + (tid & 3) * 8) * 2;
    uint32_t b_st = ((tid >> 4) * 136 + (tid & 15) * 8) * 2;
    const long a_g0 = (long)(mbase + (tid >> 2)) * KDIM + (tid & 3) * 8;
    const long b_g0 = (long)(tid >> 4) * NN + nbase + (tid & 15) * 8;
    uint32_t a_off = ((wm * 32 + (lane & 15)) * 40 + (lane >> 4) * 8) * 2;
    uint32_t b_off = ((lane & 15) * 136 + wn * 64 + (lane >> 4) * 8) * 2;

#define GM_ISSUE(k0, st)                                                        \
    {                                                                           \
        uint32_t ab = as0 + (st) * 10240, bb = bs0 + (st) * 8704;               \
        cp16(ab + a_st, A + a_g0 + (k0));                                       \
        cp16(ab + a_st + 64 * 80, A + a_g0 + 64L * KDIM + (k0));                \
        cp16(bb + b_st, Bm + b_g0 + (long)(k0) * NN);                           \
        cp16(bb + b_st + 16 * 272, Bm + b_g0 + (long)((k0) + 16) * NN);         \
        asm volatile("cp.async.commit_group;" ::);                              \
    }

    auto compute_stage = [&](int st) {
        uint32_t aa = as0 + st * 10240 + a_off;
        uint32_t bb2 = bs0 + st * 8704 + b_off;
#pragma unroll
        for (int ks = 0; ks < 2; ks++) {
            unsigned af[2][4];
            ldsm_x4(af[0], aa + ks * 32);
            ldsm_x4(af[1], aa + 1280 + ks * 32);
#pragma unroll
            for (int jp = 0; jp < 4; jp++) {
                unsigned bf[4];
                ldsm_x4t(bf, bb2 + jp * 32 + ks * 4352);
                mma_bf16(acc[0][2 * jp],     af[0], bf);
                mma_bf16(acc[0][2 * jp + 1], af[0], bf + 2);
                mma_bf16(acc[1][2 * jp],     af[1], bf);
                mma_bf16(acc[1][2 * jp + 1], af[1], bf + 2);
            }
        }
    };

    GM_ISSUE(0, 0);
    GM_ISSUE(32, 1);
    for (int it = 0; it < NIT; it += 2) {
        if (it + 2 < NIT) {
            GM_ISSUE((it + 2) * 32, (it + 2) & 3);
            GM_ISSUE((it + 3) * 32, (it + 3) & 3);
            asm volatile("cp.async.wait_group 2;" ::);
        } else {
            asm volatile("cp.async.wait_group 0;" ::);
        }
        __syncthreads();
        compute_stage(it & 3);
        compute_stage((it + 1) & 3);
        __syncthreads();
    }
#undef GM_ISSUE

    int row0 = mbase + wm * 32 + (lane >> 2);
    int col0 = nbase + wn * 64 + (lane & 3) * 2;
    if (!PV) {
        __nv_bfloat16* Vb = g_v + (long)b * CC * NN;
#pragma unroll
        for (int t = 0; t < 2; t++)
#pragma unroll
            for (int j = 0; j < 8; j++) {
                int r = row0 + t * 16, c = col0 + j * 8;
                *(__nv_bfloat162*)(Vb + (long)r * NN + c) =
                    __floats2bfloat162_rn(acc[t][j][0], acc[t][j][1]);
                *(__nv_bfloat162*)(Vb + (long)(r + 8) * NN + c) =
                    __floats2bfloat162_rn(acc[t][j][2], acc[t][j][3]);
            }
    } else {
        float* Ob = Out + (long)b * CC * NN;
        const float* Xb = Xres + (long)b * CC * NN;
        const float* rs = g_colsum + b * NN;
#pragma unroll
        for (int j = 0; j < 8; j++) {
            int c = col0 + j * 8;
            float r0 = rs[c], r1 = rs[c + 1];
#pragma unroll
            for (int t = 0; t < 2; t++) {
                int r = row0 + t * 16;
                float2 x0 = *(const float2*)(Xb + (long)r * NN + c);
                float2 o0 = {fmaf(acc[t][j][0], r0, x0.x), fmaf(acc[t][j][1], r1, x0.y)};
                *(float2*)(Ob + (long)r * NN + c) = o0;
                float2 x1 = *(const float2*)(Xb + (long)(r + 8) * NN + c);
                float2 o1 = {fmaf(acc[t][j][2], r0, x1.x), fmaf(acc[t][j][3], r1, x1.y)};
                *(float2*)(Ob + (long)(r + 8) * NN + c) = o1;
            }
        }
    }
}

// ---------------- launch -----------------------------------------------------
extern "C" void kernel_launch(void* const* d_in, const int* in_sizes, int n_in,
                              void* d_out, int out_size) {
    const float* x     = (const float*)d_in[0];
    const float* Wq    = (const float*)d_in[1];
    const float* Wk    = (const float*)d_in[2];
    const float* Wv    = (const float*)d_in[3];
    const float* gamma = (const float*)d_in[4];
    float* out = (float*)d_out;

    const int GEMM_SMEM = 4 * (10240 + 8704);  // 75776 bytes
    const int QK_SMEM   = 20480 + 17408;       // 37888 bytes (Ct needs 34816)
    cudaFuncSetAttribute(mma_gemm_kernel<512, false, true>,
                         cudaFuncAttributeMaxDynamicSharedMemorySize, GEMM_SMEM);
    cudaFuncSetAttribute(mma_gemm_kernel<4096, true, false>,
                         cudaFuncAttributeMaxDynamicSharedMemorySize, GEMM_SMEM);

    cvt_all_kernel<<<16896, 256>>>(x, Wv, Wq, Wk);
    qkproj_mma_kernel<<<dim3(32, 1, 8), 256>>>();
    qk_mma_kernel<<<dim3(32, 32, 8), 256, QK_SMEM>>>();
    // v-proj GEMM + rsum folded in as the y==4 block stripe
    mma_gemm_kernel<512, false, true><<<dim3(32, 5, 8), 256, GEMM_SMEM>>>(nullptr, nullptr, gamma);
    mma_gemm_kernel<4096, true, false><<<dim3(32, 4, 8), 256, GEMM_SMEM>>>(out, x, nullptr);
}

// round 17
// speedup vs baseline: 1.2506x; 1.0143x over previous
#include <cuda_runtime.h>
#include <cuda_bf16.h>
#include <cuda_fp16.h>
#include <cstdint>

#define BB 8
#define CC 512
#define NN 4096
#define DD 64

// ---------------- scratch ----------------------------------------------------
__device__ __nv_bfloat16 g_attn[(long)BB * NN * NN];     // 256 MB attn[n][m] = exp(qk)
__device__ __nv_bfloat16 g_xbf[(long)BB * CC * NN];      // x hi
__device__ __nv_bfloat16 g_v[(long)BB * CC * NN];
__device__ __nv_bfloat16 g_Wvbf[CC * CC];
__device__ __nv_bfloat16 g_Wqk2[128 * 1024];             // [d][hW|lW]
__device__ __half g_qt16[(long)BB * NN * DD];            // [b][n][d]
__device__ __half g_k16[(long)BB * DD * NN];             // [b][d][m]
__device__ float g_colpart[(long)BB * 64 * NN];          // 64 row-tiles now
__device__ float g_colsum[BB * NN];

// ---------------- helpers ----------------------------------------------------
__device__ __forceinline__ void ldsm_x4(unsigned r[4], uint32_t a) {
    asm volatile("ldmatrix.sync.aligned.m8n8.x4.shared.b16 {%0,%1,%2,%3}, [%4];"
                 : "=r"(r[0]), "=r"(r[1]), "=r"(r[2]), "=r"(r[3]) : "r"(a));
}
__device__ __forceinline__ void ldsm_x4t(unsigned r[4], uint32_t a) {
    asm volatile("ldmatrix.sync.aligned.m8n8.x4.trans.shared.b16 {%0,%1,%2,%3}, [%4];"
                 : "=r"(r[0]), "=r"(r[1]), "=r"(r[2]), "=r"(r[3]) : "r"(a));
}
__device__ __forceinline__ void mma_bf16(float c[4], const unsigned a[4], const unsigned b2[2]) {
    asm volatile("mma.sync.aligned.m16n8k16.row.col.f32.bf16.bf16.f32 "
                 "{%0,%1,%2,%3},{%4,%5,%6,%7},{%8,%9},{%0,%1,%2,%3};"
                 : "+f"(c[0]), "+f"(c[1]), "+f"(c[2]), "+f"(c[3])
                 : "r"(a[0]), "r"(a[1]), "r"(a[2]), "r"(a[3]), "r"(b2[0]), "r"(b2[1]));
}
__device__ __forceinline__ void mma_f16(float c[4], const unsigned a[4], const unsigned b2[2]) {
    asm volatile("mma.sync.aligned.m16n8k16.row.col.f32.f16.f16.f32 "
                 "{%0,%1,%2,%3},{%4,%5,%6,%7},{%8,%9},{%0,%1,%2,%3};"
                 : "+f"(c[0]), "+f"(c[1]), "+f"(c[2]), "+f"(c[3])
                 : "r"(a[0]), "r"(a[1]), "r"(a[2]), "r"(a[3]), "r"(b2[0]), "r"(b2[1]));
}
__device__ __forceinline__ void cp16(uint32_t s, const void* g) {
    asm volatile("cp.async.cg.shared.global [%0], [%1], 16;" :: "r"(s), "l"(g));
}
__device__ __forceinline__ uint32_t smem_u32(const void* p) {
    return (uint32_t)__cvta_generic_to_shared(p);
}

// ---------------- merged converts --------------------------------------------
__global__ void cvt_all_kernel(const float* __restrict__ x, const float* __restrict__ Wv,
                               const float* __restrict__ Wq, const float* __restrict__ Wk) {
    int bid = blockIdx.x;
    int tid = threadIdx.x;
    if (bid < 16384) {
        long i = ((long)bid * 256 + tid) * 4;
        float4 v = *(const float4*)(x + i);
        *(__nv_bfloat162*)(g_xbf + i)     = __floats2bfloat162_rn(v.x, v.y);
        *(__nv_bfloat162*)(g_xbf + i + 2) = __floats2bfloat162_rn(v.z, v.w);
    } else if (bid < 16640) {
        long i = ((long)(bid - 16384) * 256 + tid) * 4;
        float4 v = *(const float4*)(Wv + i);
        *(__nv_bfloat162*)(g_Wvbf + i)     = __floats2bfloat162_rn(v.x, v.y);
        *(__nv_bfloat162*)(g_Wvbf + i + 2) = __floats2bfloat162_rn(v.z, v.w);
    } else {
        int i = (bid - 16640) * 256 + tid;
        int d = i >> 9, c = i & 511;
        float v = (d < 64) ? Wq[d * 512 + c] : Wk[(d - 64) * 512 + c];
        __nv_bfloat16 h = __float2bfloat16(v);
        __nv_bfloat16 l = __float2bfloat16(v - __bfloat162float(h));
        g_Wqk2[d * 1024 + c] = h;
        g_Wqk2[d * 1024 + 512 + c] = l;
    }
}

// ---------------- qk projection (2-term split GEMM K=1024), 2-stage ----------
__global__ __launch_bounds__(256, 2)
void qkproj_mma_kernel() {
    constexpr int NIT = 32;
    __shared__ __align__(16) __nv_bfloat16 As[2 * 128 * 40];
    __shared__ __align__(16) __nv_bfloat16 Bs[2 * 32 * 136];
    __shared__ __align__(16) __half tq[128 * 68];    // [n-local][d], stride 68
    int b = blockIdx.z;
    int nbase = blockIdx.x * 128;
    int tid = threadIdx.x, lane = tid & 31, warp = tid >> 5;
    int wm = warp & 3, wn = warp >> 2;
    const __nv_bfloat16* xh = g_xbf + (long)b * CC * NN;

    float acc[2][8][4];
#pragma unroll
    for (int t = 0; t < 2; t++)
#pragma unroll
        for (int j = 0; j < 8; j++)
#pragma unroll
            for (int e = 0; e < 4; e++) acc[t][j][e] = 0.f;

    uint32_t as0 = smem_u32(As), bs0 = smem_u32(Bs);
    uint32_t a_st = ((tid >> 2) * 40 + (tid & 3) * 8) * 2;
    uint32_t b_st = ((tid >> 4) * 136 + (tid & 15) * 8) * 2;
    const long a_g0 = (long)(tid >> 2) * 1024 + (tid & 3) * 8;
    const long b_g0 = (long)(tid >> 4) * NN + nbase + (tid & 15) * 8;
    uint32_t a_off = ((wm * 32 + (lane & 15)) * 40 + (lane >> 4) * 8) * 2;
    uint32_t b_off = ((lane & 15) * 136 + wn * 64 + (lane >> 4) * 8) * 2;

    auto issue = [&](int c, int st) {
        uint32_t ab = as0 + st * 10240, bb = bs0 + st * 8704;
        cp16(ab + a_st, g_Wqk2 + a_g0 + c * 32);
        cp16(ab + a_st + 64 * 80, g_Wqk2 + a_g0 + 64L * 1024 + c * 32);
        const __nv_bfloat16* Bsrc = xh + (long)((c & 15) * 32) * NN;
        cp16(bb + b_st, Bsrc + b_g0);
        cp16(bb + b_st + 16 * 272, Bsrc + b_g0 + 16L * NN);
        asm volatile("cp.async.commit_group;" ::);
    };

    issue(0, 0);
    for (int it = 0; it < NIT; it++) {
        if (it + 1 < NIT) {
            issue(it + 1, (it + 1) & 1);
            asm volatile("cp.async.wait_group 1;" ::);
        } else {
            asm volatile("cp.async.wait_group 0;" ::);
        }
        __syncthreads();
        uint32_t aa = as0 + (it & 1) * 10240 + a_off;
        uint32_t bb2 = bs0 + (it & 1) * 8704 + b_off;
#pragma unroll
        for (int ks = 0; ks < 2; ks++) {
            unsigned af[2][4];
            ldsm_x4(af[0], aa + ks * 32);
            ldsm_x4(af[1], aa + 1280 + ks * 32);
#pragma unroll
            for (int jp = 0; jp < 4; jp++) {
                unsigned bf[4];
                ldsm_x4t(bf, bb2 + jp * 32 + ks * 4352);
                mma_bf16(acc[0][2 * jp],     af[0], bf);
                mma_bf16(acc[0][2 * jp + 1], af[0], bf + 2);
                mma_bf16(acc[1][2 * jp],     af[1], bf);
                mma_bf16(acc[1][2 * jp + 1], af[1], bf + 2);
            }
        }
        __syncthreads();
    }

    int row0 = wm * 32 + (lane >> 2);
    int col0l = wn * 64 + (lane & 3) * 2;
#pragma unroll
    for (int t = 0; t < 2; t++)
#pragma unroll
        for (int rr = 0; rr < 2; rr++) {
            int d = row0 + t * 16 + rr * 8;
            if (d < 64) {
#pragma unroll
                for (int j = 0; j < 8; j++) {
                    int c = col0l + j * 8;
                    tq[c * 68 + d]       = __float2half(acc[t][j][rr * 2]);
                    tq[(c + 1) * 68 + d] = __float2half(acc[t][j][rr * 2 + 1]);
                }
            } else {
                __half* dst = g_k16 + ((long)b * DD + d - 64) * NN + nbase;
#pragma unroll
                for (int j = 0; j < 8; j++) {
                    *(__half2*)(dst + col0l + j * 8) =
                        __floats2half2_rn(acc[t][j][rr * 2], acc[t][j][rr * 2 + 1]);
                }
            }
        }
    __syncthreads();
    {
        int n = tid >> 1, dh = (tid & 1) * 32;
        __half* dst = g_qt16 + (long)b * NN * DD + (long)(nbase + n) * DD + dh;
        const __half* src = tq + n * 68 + dh;
#pragma unroll
        for (int c4 = 0; c4 < 8; c4++)
            *(uint2*)(dst + c4 * 4) = *(const uint2*)(src + c4 * 4);
    }
}

// ---------------- qk fp16 GEMM: 64n x 128m tile, 3 CTAs/SM -------------------
// dynamic smem: 2 stages A(4096B->5120 w/stride)+B(8704B); Ct (64x136) aliases.
__global__ __launch_bounds__(256, 3)
void qk_mma_kernel() {
    constexpr int KD = 64;
    constexpr int CTS = 136;
    extern __shared__ __align__(16) char qsm[];
    __half* As = (__half*)qsm;                 // 2 * 64*40 halfs = 2*5120B
    __half* Bs = (__half*)(qsm + 10240);       // 2 * 32*136 halfs = 2*8704B
    __nv_bfloat16* Ct = (__nv_bfloat16*)qsm;   // 64*136*2 = 17408B, post-loop
    __shared__ float cred[2 * 128];
    int b = blockIdx.z;
    const __half* A  = g_qt16 + (long)b * NN * KD;   // [n][64]
    const __half* Bm = g_k16  + (long)b * KD * NN;   // [d][m]
    int mbase = blockIdx.y * 64;   // n (softmax axis), 64-row tile
    int nbase = blockIdx.x * 128;  // m
    int tid = threadIdx.x, lane = tid & 31, warp = tid >> 5;
    int wm = warp & 1, wn = warp >> 1;   // 2 x 4 warp grid, per-warp 32n x 32m

    float acc[2][4][4];
#pragma unroll
    for (int t = 0; t < 2; t++)
#pragma unroll
        for (int j = 0; j < 4; j++)
#pragma unroll
            for (int e = 0; e < 4; e++) acc[t][j][e] = 0.f;

    uint32_t as0 = smem_u32(As), bs0 = smem_u32(Bs);
    uint32_t a_st = ((tid >> 2) * 40 + (tid & 3) * 8) * 2;
    uint32_t b_st = ((tid >> 4) * 136 + (tid & 15) * 8) * 2;
    const long a_g0 = (long)(mbase + (tid >> 2)) * KD + (tid & 3) * 8;
    const long b_g0 = (long)(tid >> 4) * NN + nbase + (tid & 15) * 8;
    uint32_t a_off = ((wm * 32 + (lane & 15)) * 40 + (lane >> 4) * 8) * 2;
    uint32_t b_off = ((lane & 15) * 136 + wn * 32 + (lane >> 4) * 8) * 2;

#define QK_ISSUE(k0, st)                                                        \
    {                                                                           \
        uint32_t ab = as0 + (st) * 5120, bb = bs0 + (st) * 8704;                \
        cp16(ab + a_st, A + a_g0 + (k0));                                       \
        cp16(bb + b_st, Bm + b_g0 + (long)(k0) * NN);                           \
        cp16(bb + b_st + 16 * 272, Bm + b_g0 + (long)((k0) + 16) * NN);         \
        asm volatile("cp.async.commit_group;" ::);                              \
    }

    QK_ISSUE(0, 0);
    QK_ISSUE(32, 1);
#pragma unroll
    for (int it = 0; it < 2; it++) {
        if (it == 0) {
            asm volatile("cp.async.wait_group 1;" ::);
        } else {
            asm volatile("cp.async.wait_group 0;" ::);
        }
        __syncthreads();
        uint32_t aa = as0 + it * 5120 + a_off;
        uint32_t bbq = bs0 + it * 8704 + b_off;
#pragma unroll
        for (int ks = 0; ks < 2; ks++) {
            unsigned af[2][4];
            ldsm_x4(af[0], aa + ks * 32);
            ldsm_x4(af[1], aa + 1280 + ks * 32);
#pragma unroll
            for (int jp = 0; jp < 2; jp++) {
                unsigned bf[4];
                ldsm_x4t(bf, bbq + jp * 32 + ks * 4352);
                mma_f16(acc[0][2 * jp],     af[0], bf);
                mma_f16(acc[0][2 * jp + 1], af[0], bf + 2);
                mma_f16(acc[1][2 * jp],     af[1], bf);
                mma_f16(acc[1][2 * jp + 1], af[1], bf + 2);
            }
        }
    }
#undef QK_ISSUE

    __syncthreads();   // As/Bs reads done before Ct aliases them

    // exp -> Ct (smem), column partial sums
    int row0l = wm * 32 + (lane >> 2);
    int col0l = wn * 32 + (lane & 3) * 2;
    float colp[4][2];
#pragma unroll
    for (int j = 0; j < 4; j++) { colp[j][0] = 0.f; colp[j][1] = 0.f; }
#pragma unroll
    for (int t = 0; t < 2; t++)
#pragma unroll
        for (int j = 0; j < 4; j++) {
            float e0 = __expf(acc[t][j][0]);
            float e1 = __expf(acc[t][j][1]);
            float e2 = __expf(acc[t][j][2]);
            float e3 = __expf(acc[t][j][3]);
            colp[j][0] += e0 + e2;
            colp[j][1] += e1 + e3;
            int r = row0l + t * 16, c = col0l + j * 8;
            *(__nv_bfloat162*)(Ct + r * CTS + c)       = __floats2bfloat162_rn(e0, e1);
            *(__nv_bfloat162*)(Ct + (r + 8) * CTS + c) = __floats2bfloat162_rn(e2, e3);
        }
#pragma unroll
    for (int off = 16; off >= 4; off >>= 1)
#pragma unroll
        for (int j = 0; j < 4; j++) {
            colp[j][0] += __shfl_xor_sync(0xffffffffu, colp[j][0], off);
            colp[j][1] += __shfl_xor_sync(0xffffffffu, colp[j][1], off);
        }
    if ((lane >> 2) == 0) {
#pragma unroll
        for (int j = 0; j < 4; j++) {
            cred[wm * 128 + wn * 32 + j * 8 + (lane & 3) * 2]     = colp[j][0];
            cred[wm * 128 + wn * 32 + j * 8 + (lane & 3) * 2 + 1] = colp[j][1];
        }
    }
    __syncthreads();

    // coalesced attn store: 4 threads per row, 4 x 16B chunks each
    __nv_bfloat16* ab = g_attn + ((long)b << 24);
    {
        int row = tid >> 2;
        int quarter = tid & 3;
        const __nv_bfloat16* src = Ct + row * CTS;
        __nv_bfloat16* dstg = ab + (long)(mbase + row) * NN + nbase;
#pragma unroll
        for (int j2 = 0; j2 < 4; j2++) {
            int cchunk = (quarter + 4 * j2) * 8;
            *(uint4*)(dstg + cchunk) = *(const uint4*)(src + cchunk);
        }
    }
    if (tid < 128) {
        g_colpart[((long)b * 64 + blockIdx.y) * NN + nbase + tid] =
            cred[tid] + cred[128 + tid];
    }
}

// ---------------- bf16 tensor GEMM (v-proj / PV), 4-stage paired-iter --------
// RSUM=true adds a y==4 stripe that only finalizes colsum.
template <int KDIM, bool PV, bool RSUM>
__global__ __launch_bounds__(256)
void mma_gemm_kernel(float* __restrict__ Out, const float* __restrict__ Xres,
                     const float* __restrict__ gamma) {
    constexpr int NIT = KDIM / 32;
    if (RSUM && blockIdx.y == 4) {
        int idx = (blockIdx.x + 32 * blockIdx.z) * 256 + threadIdx.x;
        if (idx < 32768) {
            int b = idx >> 12, col = idx & 4095;
            const float* p = g_colpart + (long)b * 64 * NN + col;
            float s = 0.f;
#pragma unroll
            for (int t = 0; t < 64; t++) s += p[(long)t * NN];
            g_colsum[idx] = gamma[0] / s;
        }
        return;
    }
    extern __shared__ __align__(16) char dsm[];
    __nv_bfloat16* As = (__nv_bfloat16*)dsm;       // 4 * 5120 bf16
    __nv_bfloat16* Bs = As + 4 * 5120;             // 4 * 4352 bf16
    int b = blockIdx.z;
    const __nv_bfloat16* A  = PV ? (g_v + (long)b * CC * NN) : g_Wvbf;
    const __nv_bfloat16* Bm = PV ? (g_attn + ((long)b << 24)) : (g_xbf + (long)b * CC * NN);
    int mbase = blockIdx.y * 128, nbase = blockIdx.x * 128;
    int tid = threadIdx.x, lane = tid & 31, warp = tid >> 5;
    int wm = warp & 3, wn = warp >> 2;

    float acc[2][8][4];
#pragma unroll
    for (int t = 0; t < 2; t++)
#pragma unroll
        for (int j = 0; j < 8; j++)
#pragma unroll
            for (int e = 0; e < 4; e++) acc[t][j][e] = 0.f;

    uint32_t as0 = smem_u32(As), bs0 = smem_u32(Bs);
    uint32_t a_st = ((tid >> 2) * 40 + (tid & 3) * 8) * 2;
    uint32_t b_st = ((tid >> 4) * 136 + (tid & 15) * 8) * 2;
    const long a_g0 = (long)(mbase + (tid >> 2)) * KDIM + (tid & 3) * 8;
    const long b_g0 = (long)(tid >> 4) * NN + nbase + (tid & 15) * 8;
    uint32_t a_off = ((wm * 32 + (lane & 15)) * 40 + (lane >> 4) * 8) * 2;
    uint32_t b_off = ((lane & 15) * 136 + wn * 64 + (lane >> 4) * 8) * 2;

#define GM_ISSUE(k0, st)                                                        \
    {                                                                           \
        uint32_t ab = as0 + (st) * 10240, bb = bs0 + (st) * 8704;               \
        cp16(ab + a_st, A + a_g0 + (k0));                                       \
        cp16(ab + a_st + 64 * 80, A + a_g0 + 64L * KDIM + (k0));                \
        cp16(bb + b_st, Bm + b_g0 + (long)(k0) * NN);                           \
        cp16(bb + b_st + 16 * 272, Bm + b_g0 + (long)((k0) + 16) * NN);         \
        asm volatile("cp.async.commit_group;" ::);                              \
    }

    auto compute_stage = [&](int st) {
        uint32_t aa = as0 + st * 10240 + a_off;
        uint32_t bb2 = bs0 + st * 8704 + b_off;
#pragma unroll
        for (int ks = 0; ks < 2; ks++) {
            unsigned af[2][4];
            ldsm_x4(af[0], aa + ks * 32);
            ldsm_x4(af[1], aa + 1280 + ks * 32);
#pragma unroll
            for (int jp = 0; jp < 4; jp++) {
                unsigned bf[4];
                ldsm_x4t(bf, bb2 + jp * 32 + ks * 4352);
                mma_bf16(acc[0][2 * jp],     af[0], bf);
                mma_bf16(acc[0][2 * jp + 1], af[0], bf + 2);
                mma_bf16(acc[1][2 * jp],     af[1], bf);
                mma_bf16(acc[1][2 * jp + 1], af[1], bf + 2);
            }
        }
    };

    GM_ISSUE(0, 0);
    GM_ISSUE(32, 1);
    for (int it = 0; it < NIT; it += 2) {
        if (it + 2 < NIT) {
            GM_ISSUE((it + 2) * 32, (it + 2) & 3);
            GM_ISSUE((it + 3) * 32, (it + 3) & 3);
            asm volatile("cp.async.wait_group 2;" ::);
        } else {
            asm volatile("cp.async.wait_group 0;" ::);
        }
        __syncthreads();
        compute_stage(it & 3);
        compute_stage((it + 1) & 3);
        __syncthreads();
    }
#undef GM_ISSUE

    int row0 = mbase + wm * 32 + (lane >> 2);
    int col0 = nbase + wn * 64 + (lane & 3) * 2;
    if (!PV) {
        __nv_bfloat16* Vb = g_v + (long)b * CC * NN;
#pragma unroll
        for (int t = 0; t < 2; t++)
#pragma unroll
            for (int j = 0; j < 8; j++) {
                int r = row0 + t * 16, c = col0 + j * 8;
                *(__nv_bfloat162*)(Vb + (long)r * NN + c) =
                    __floats2bfloat162_rn(acc[t][j][0], acc[t][j][1]);
                *(__nv_bfloat162*)(Vb + (long)(r + 8) * NN + c) =
                    __floats2bfloat162_rn(acc[t][j][2], acc[t][j][3]);
            }
    } else {
        float* Ob = Out + (long)b * CC * NN;
        const float* Xb = Xres + (long)b * CC * NN;
        const float* rs = g_colsum + b * NN;
#pragma unroll
        for (int j = 0; j < 8; j++) {
            int c = col0 + j * 8;
            float r0 = rs[c], r1 = rs[c + 1];
#pragma unroll
            for (int t = 0; t < 2; t++) {
                int r = row0 + t * 16;
                float2 x0 = *(const float2*)(Xb + (long)r * NN + c);
                float2 o0 = {fmaf(acc[t][j][0], r0, x0.x), fmaf(acc[t][j][1], r1, x0.y)};
                *(float2*)(Ob + (long)r * NN + c) = o0;
                float2 x1 = *(const float2*)(Xb + (long)(r + 8) * NN + c);
                float2 o1 = {fmaf(acc[t][j][2], r0, x1.x), fmaf(acc[t][j][3], r1, x1.y)};
                *(float2*)(Ob + (long)(r + 8) * NN + c) = o1;
            }
        }
    }
}

// ---------------- launch -----------------------------------------------------
extern "C" void kernel_launch(void* const* d_in, const int* in_sizes, int n_in,
                              void* d_out, int out_size) {
    const float* x     = (const float*)d_in[0];
    const float* Wq    = (const float*)d_in[1];
    const float* Wk    = (const float*)d_in[2];
    const float* Wv    = (const float*)d_in[3];
    const float* gamma = (const float*)d_in[4];
    float* out = (float*)d_out;

    const int GEMM_SMEM = 4 * (10240 + 8704);  // 75776 bytes
    const int QK_SMEM   = 2 * (5120 + 8704);   // 27648 bytes (Ct needs 17408)
    cudaFuncSetAttribute(mma_gemm_kernel<512, false, true>,
                         cudaFuncAttributeMaxDynamicSharedMemorySize, GEMM_SMEM);
    cudaFuncSetAttribute(mma_gemm_kernel<4096, true, false>,
                         cudaFuncAttributeMaxDynamicSharedMemorySize, GEMM_SMEM);
    cudaFuncSetAttribute(qk_mma_kernel,
                         cudaFuncAttributeMaxDynamicSharedMemorySize, QK_SMEM);

    cvt_all_kernel<<<16896, 256>>>(x, Wv, Wq, Wk);
    qkproj_mma_kernel<<<dim3(32, 1, 8), 256>>>();
    qk_mma_kernel<<<dim3(32, 64, 8), 256, QK_SMEM>>>();
    // v-proj GEMM + rsum folded in as the y==4 block stripe
    mma_gemm_kernel<512, false, true><<<dim3(32, 5, 8), 256, GEMM_SMEM>>>(nullptr, nullptr, gamma);
    mma_gemm_kernel<4096, true, false><<<dim3(32, 4, 8), 256, GEMM_SMEM>>>(out, x, nullptr);
}